// round 1
// baseline (speedup 1.0000x reference)
#include <cuda_runtime.h>
#include <math.h>

// ---------------------------------------------------------------------------
// MLA forward, fp32 baseline.
//   B=2, T=2048, C=2048, H=16, DH=128, L=512, hd2=64
// Pipeline:
//   kv_d = x @ W_kvD^T            [4096,512]
//   q_d  = x @ W_qD^T             [4096,512]
//   k_c  = kv_d @ W_kU^T          [4096,1024]
//   q_c  = q_d  @ W_qU^T          [4096,1024]
//   v    = kv_d @ W_vU^T          [4096,2048]
//   k_r  = rope(x   @ W_rk^T)     [4096,1024]
//   q_r  = rope(q_d @ W_rq^T)     [4096,1024]
//   Q/K  = concat per head -> [B,H,T,128] ; V -> [B,H,T,128]
//   attn = causal softmax(QK^T/sqrt(128)) V  -> [B,T,2048]
//   out  = attn @ W_o^T           [4096,2048]
// ---------------------------------------------------------------------------

#define Bb 2
#define Tt 2048
#define Cc 2048
#define Hh 16
#define Dh 128
#define BT 4096   // B*T

// ---------------- scratch (device globals; no cudaMalloc allowed) ----------
__device__ float g_kvd [BT * 512];
__device__ float g_qd  [BT * 512];
__device__ float g_kc  [BT * 1024];
__device__ float g_qc  [BT * 1024];
__device__ float g_v   [BT * 2048];
__device__ float g_krr [BT * 1024];
__device__ float g_qrr [BT * 1024];
__device__ float g_Q   [BT * 2048];   // [B,H,T,128]
__device__ float g_K   [BT * 2048];   // [B,H,T,128]
__device__ float g_V   [BT * 2048];   // [B,H,T,128]
__device__ float g_attn[BT * 2048];   // [B,T,C]

// ---------------------------------------------------------------------------
// Generic tiled SGEMM:  C[M,N] = A[M,K] @ W[N,K]^T
// BM=BN=128, BK=16, 256 threads, 8x8 register tile per thread.
// smem pitch 132 (16B aligned, kills 512B same-bank pathology).
// ---------------------------------------------------------------------------
__global__ void __launch_bounds__(256)
sgemm_tn(const float* __restrict__ A, const float* __restrict__ W,
         float* __restrict__ C, int M, int N, int K)
{
    __shared__ float As[16][132];
    __shared__ float Bs[16][132];

    const int tid = threadIdx.x;
    const int tx  = tid & 15;
    const int ty  = tid >> 4;
    const int m0  = blockIdx.y * 128;
    const int n0  = blockIdx.x * 128;

    const int lr = tid >> 2;         // 0..63 : row index for fills
    const int lk = (tid & 3) * 4;    // 0,4,8,12 : k quad

    float acc[8][8];
#pragma unroll
    for (int i = 0; i < 8; i++)
#pragma unroll
        for (int j = 0; j < 8; j++) acc[i][j] = 0.f;

    for (int k0 = 0; k0 < K; k0 += 16) {
        // ---- fill (transposed): As[k][m] = A[m0+m][k0+k] -------------------
#pragma unroll
        for (int it = 0; it < 2; it++) {
            const int m = lr + it * 64;
            float4 av = *(const float4*)&A[(size_t)(m0 + m) * K + k0 + lk];
            As[lk + 0][m] = av.x; As[lk + 1][m] = av.y;
            As[lk + 2][m] = av.z; As[lk + 3][m] = av.w;
            float4 bv = *(const float4*)&W[(size_t)(n0 + m) * K + k0 + lk];
            Bs[lk + 0][m] = bv.x; Bs[lk + 1][m] = bv.y;
            Bs[lk + 2][m] = bv.z; Bs[lk + 3][m] = bv.w;
        }
        __syncthreads();

        // ---- compute -------------------------------------------------------
#pragma unroll
        for (int kk = 0; kk < 16; kk++) {
            float a[8], b[8];
            *(float4*)&a[0] = *(const float4*)&As[kk][4 * ty];
            *(float4*)&a[4] = *(const float4*)&As[kk][64 + 4 * ty];
            *(float4*)&b[0] = *(const float4*)&Bs[kk][4 * tx];
            *(float4*)&b[4] = *(const float4*)&Bs[kk][64 + 4 * tx];
#pragma unroll
            for (int i = 0; i < 8; i++)
#pragma unroll
                for (int j = 0; j < 8; j++)
                    acc[i][j] += a[i] * b[j];
        }
        __syncthreads();
    }

    // ---- writeback ---------------------------------------------------------
#pragma unroll
    for (int i = 0; i < 8; i++) {
        const int m = m0 + ((i < 4) ? (4 * ty + i) : (64 + 4 * ty + (i - 4)));
        float4 v0 = make_float4(acc[i][0], acc[i][1], acc[i][2], acc[i][3]);
        float4 v1 = make_float4(acc[i][4], acc[i][5], acc[i][6], acc[i][7]);
        *(float4*)&C[(size_t)m * N + n0 + 4 * tx]      = v0;
        *(float4*)&C[(size_t)m * N + n0 + 64 + 4 * tx] = v1;
    }
}

// ---------------------------------------------------------------------------
// Assemble Q or K: out[b,h,t, 0:64] = cpart[b,t, h*64 + 0:64]
//                  out[b,h,t,64:128] = rope(rraw[b,t, h*64 + 0:64])
// RoPE is interleaved over the FULL 1024-dim vector: pair j0=h*64+2p,
// freq = exp(j0 * (-ln(10000)/1024)), angle = t * freq.
// One thread per pair p in [0,32): writes 4 floats.
// ---------------------------------------------------------------------------
__global__ void __launch_bounds__(256)
assemble_qk(const float* __restrict__ cpart, const float* __restrict__ rraw,
            float* __restrict__ outp)
{
    const int idx = blockIdx.x * blockDim.x + threadIdx.x; // B*T*H*32
    const int p = idx & 31;
    const int h = (idx >> 5) & (Hh - 1);
    const int t = (idx >> 9) & (Tt - 1);
    const int b = idx >> 20;

    const int inrow = ((b * Tt + t) << 10) + (h << 6);       // *1024 + h*64
    const int ob    = (((b * Hh + h) * Tt + t) << 7);        // *128

    float2 cv = *(const float2*)&cpart[inrow + 2 * p];
    *(float2*)&outp[ob + 2 * p] = cv;

    float2 rv = *(const float2*)&rraw[inrow + 2 * p];
    const int j0 = (h << 6) + 2 * p;
    const float kfc = -0.00899447225546836f;                 // -ln(10000)/1024
    float freq = expf((float)j0 * kfc);
    float ang  = (float)t * freq;
    float s, c;
    sincosf(ang, &s, &c);
    float2 o;
    o.x = rv.x * c - rv.y * s;
    o.y = rv.y * c + rv.x * s;
    *(float2*)&outp[ob + 64 + 2 * p] = o;
}

// V transpose: V[b,h,t,d] = v[b,t, h*128 + d], one float4 per thread.
__global__ void __launch_bounds__(256)
assemble_v(const float* __restrict__ vin, float* __restrict__ vout)
{
    const int idx = blockIdx.x * blockDim.x + threadIdx.x; // B*H*T*32
    const int d4 = idx & 31;
    const int t  = (idx >> 5) & (Tt - 1);
    const int h  = (idx >> 16) & (Hh - 1);
    const int b  = idx >> 20;
    float4 v = *(const float4*)&vin[(size_t)((b * Tt + t) * Cc) + h * Dh + d4 * 4];
    *(float4*)&vout[(size_t)idx * 4] = v;
}

// ---------------------------------------------------------------------------
// Causal flash attention, fp32 SIMT.
// Block: 256 threads, one (b,h,qtile) with BQ=64, BKV=64, D=128.
// Layouts: Qs/Ks/Vs [64][132], Ss [64][65]. Online softmax, O in registers.
// ---------------------------------------------------------------------------
#define ATTN_SMEM_FLOATS (3 * 64 * 132 + 64 * 65 + 3 * 64)
#define ATTN_SMEM_BYTES  (ATTN_SMEM_FLOATS * 4)

__global__ void __launch_bounds__(256)
attn_kernel(const float* __restrict__ Q, const float* __restrict__ K,
            const float* __restrict__ V, float* __restrict__ Aout)
{
    extern __shared__ float smem[];
    float* Qs = smem;                 // 64*132
    float* Ks = Qs + 64 * 132;        // 64*132
    float* Vs = Ks + 64 * 132;        // 64*132
    float* Ss = Vs + 64 * 132;        // 64*65
    float* sM = Ss + 64 * 65;         // 64
    float* sL = sM + 64;              // 64
    float* sA = sL + 64;              // 64

    const int qt  = gridDim.x - 1 - blockIdx.x;  // longest blocks first
    const int bh  = blockIdx.y;
    const int tid = threadIdx.x;
    const int tx  = tid & 15;
    const int ty  = tid >> 4;
    const float scale = 0.08838834764831845f;    // 1/sqrt(128)

    const float* Qg = Q + ((size_t)bh * Tt + qt * 64) * Dh;
    const float* Kg = K + (size_t)bh * Tt * Dh;
    const float* Vg = V + (size_t)bh * Tt * Dh;

    // load Q tile
    for (int i = tid; i < 64 * 32; i += 256) {
        const int r = i >> 5, d4 = i & 31;
        *(float4*)&Qs[r * 132 + d4 * 4] = *(const float4*)&Qg[r * Dh + d4 * 4];
    }
    if (tid < 64) { sM[tid] = -1e30f; sL[tid] = 0.f; }

    float o[4][8];
#pragma unroll
    for (int i = 0; i < 4; i++)
#pragma unroll
        for (int j = 0; j < 8; j++) o[i][j] = 0.f;

    __syncthreads();

    const int ntiles = qt + 1;
    for (int kt = 0; kt < ntiles; kt++) {
        // ---- fill K,V tiles ------------------------------------------------
        for (int i = tid; i < 64 * 32; i += 256) {
            const int r = i >> 5, d4 = i & 31;
            *(float4*)&Ks[r * 132 + d4 * 4] =
                *(const float4*)&Kg[(kt * 64 + r) * Dh + d4 * 4];
            *(float4*)&Vs[r * 132 + d4 * 4] =
                *(const float4*)&Vg[(kt * 64 + r) * Dh + d4 * 4];
        }
        __syncthreads();

        // ---- S = Q K^T (4x4 per thread; cols strided tx+16j) ---------------
        float acc[4][4];
#pragma unroll
        for (int i = 0; i < 4; i++)
#pragma unroll
            for (int j = 0; j < 4; j++) acc[i][j] = 0.f;

        for (int d4 = 0; d4 < 32; d4++) {
            float4 qf[4], kf[4];
#pragma unroll
            for (int i = 0; i < 4; i++)
                qf[i] = *(const float4*)&Qs[(4 * ty + i) * 132 + d4 * 4];
#pragma unroll
            for (int j = 0; j < 4; j++)
                kf[j] = *(const float4*)&Ks[(tx + 16 * j) * 132 + d4 * 4];
#pragma unroll
            for (int i = 0; i < 4; i++)
#pragma unroll
                for (int j = 0; j < 4; j++) {
                    acc[i][j] += qf[i].x * kf[j].x;
                    acc[i][j] += qf[i].y * kf[j].y;
                    acc[i][j] += qf[i].z * kf[j].z;
                    acc[i][j] += qf[i].w * kf[j].w;
                }
        }

        // mask + scale, write to Ss
#pragma unroll
        for (int i = 0; i < 4; i++) {
            const int r  = 4 * ty + i;
            const int qg = qt * 64 + r;
#pragma unroll
            for (int j = 0; j < 4; j++) {
                const int c  = tx + 16 * j;
                const int sg = kt * 64 + c;
                Ss[r * 65 + c] = (sg <= qg) ? acc[i][j] * scale : -1e30f;
            }
        }
        __syncthreads();

        // ---- online softmax: 4 threads per row -----------------------------
        {
            const int r  = tid >> 2;
            const int qd = tid & 3;
            float tmax = -1e30f;
#pragma unroll
            for (int c0 = 0; c0 < 16; c0++)
                tmax = fmaxf(tmax, Ss[r * 65 + qd * 16 + c0]);
            tmax = fmaxf(tmax, __shfl_xor_sync(0xffffffffu, tmax, 1));
            tmax = fmaxf(tmax, __shfl_xor_sync(0xffffffffu, tmax, 2));

            const float m_old = sM[r];
            const float m_new = fmaxf(m_old, tmax);
            float psum = 0.f;
#pragma unroll
            for (int c0 = 0; c0 < 16; c0++) {
                float p = expf(Ss[r * 65 + qd * 16 + c0] - m_new);
                Ss[r * 65 + qd * 16 + c0] = p;
                psum += p;
            }
            psum += __shfl_xor_sync(0xffffffffu, psum, 1);
            psum += __shfl_xor_sync(0xffffffffu, psum, 2);
            if (qd == 0) {
                const float alpha = expf(m_old - m_new);
                sA[r] = alpha;
                sM[r] = m_new;
                sL[r] = sL[r] * alpha + psum;
            }
        }
        __syncthreads();

        // ---- O = O*alpha + P @ V ------------------------------------------
#pragma unroll
        for (int i = 0; i < 4; i++) {
            const float al = sA[4 * ty + i];
#pragma unroll
            for (int j = 0; j < 8; j++) o[i][j] *= al;
        }
        for (int c = 0; c < 64; c++) {
            float p[4];
#pragma unroll
            for (int i = 0; i < 4; i++) p[i] = Ss[(4 * ty + i) * 65 + c];
            float4 v0 = *(const float4*)&Vs[c * 132 + 4 * tx];
            float4 v1 = *(const float4*)&Vs[c * 132 + 64 + 4 * tx];
#pragma unroll
            for (int i = 0; i < 4; i++) {
                o[i][0] += p[i] * v0.x;  o[i][1] += p[i] * v0.y;
                o[i][2] += p[i] * v0.z;  o[i][3] += p[i] * v0.w;
                o[i][4] += p[i] * v1.x;  o[i][5] += p[i] * v1.y;
                o[i][6] += p[i] * v1.z;  o[i][7] += p[i] * v1.w;
            }
        }
        __syncthreads();   // protect Ks/Vs/Ss before next fill
    }

    // ---- epilogue: normalize, write attn[b,t, h*128+d] ---------------------
    const int b = bh >> 4;
    const int h = bh & 15;
#pragma unroll
    for (int i = 0; i < 4; i++) {
        const int r = 4 * ty + i;
        const float inv = 1.f / sL[r];
        const int t = qt * 64 + r;
        float* dst = Aout + (size_t)(b * Tt + t) * Cc + h * Dh;
        float4 v0 = make_float4(o[i][0] * inv, o[i][1] * inv,
                                o[i][2] * inv, o[i][3] * inv);
        float4 v1 = make_float4(o[i][4] * inv, o[i][5] * inv,
                                o[i][6] * inv, o[i][7] * inv);
        *(float4*)&dst[4 * tx]      = v0;
        *(float4*)&dst[64 + 4 * tx] = v1;
    }
}

// ---------------------------------------------------------------------------
// host launch
// ---------------------------------------------------------------------------
extern "C" void kernel_launch(void* const* d_in, const int* in_sizes, int n_in,
                              void* d_out, int out_size)
{
    const float* x     = (const float*)d_in[0];
    const float* W_kvD = (const float*)d_in[1];
    const float* W_qD  = (const float*)d_in[2];
    const float* W_kU  = (const float*)d_in[3];
    const float* W_vU  = (const float*)d_in[4];
    const float* W_qU  = (const float*)d_in[5];
    const float* W_rk  = (const float*)d_in[6];
    const float* W_rq  = (const float*)d_in[7];
    const float* W_o   = (const float*)d_in[8];
    float* out = (float*)d_out;

    float *kvd, *qd, *kc, *qc, *v, *krr, *qrr, *Qh, *Kh, *Vh, *attn;
    cudaGetSymbolAddress((void**)&kvd,  g_kvd);
    cudaGetSymbolAddress((void**)&qd,   g_qd);
    cudaGetSymbolAddress((void**)&kc,   g_kc);
    cudaGetSymbolAddress((void**)&qc,   g_qc);
    cudaGetSymbolAddress((void**)&v,    g_v);
    cudaGetSymbolAddress((void**)&krr,  g_krr);
    cudaGetSymbolAddress((void**)&qrr,  g_qrr);
    cudaGetSymbolAddress((void**)&Qh,   g_Q);
    cudaGetSymbolAddress((void**)&Kh,   g_K);
    cudaGetSymbolAddress((void**)&Vh,   g_V);
    cudaGetSymbolAddress((void**)&attn, g_attn);

    // down/up projections
    sgemm_tn<<<dim3( 512 / 128, BT / 128), 256>>>(x,   W_kvD, kvd, BT,  512, 2048);
    sgemm_tn<<<dim3( 512 / 128, BT / 128), 256>>>(x,   W_qD,  qd,  BT,  512, 2048);
    sgemm_tn<<<dim3(1024 / 128, BT / 128), 256>>>(x,   W_rk,  krr, BT, 1024, 2048);
    sgemm_tn<<<dim3(1024 / 128, BT / 128), 256>>>(kvd, W_kU,  kc,  BT, 1024,  512);
    sgemm_tn<<<dim3(2048 / 128, BT / 128), 256>>>(kvd, W_vU,  v,   BT, 2048,  512);
    sgemm_tn<<<dim3(1024 / 128, BT / 128), 256>>>(qd,  W_qU,  qc,  BT, 1024,  512);
    sgemm_tn<<<dim3(1024 / 128, BT / 128), 256>>>(qd,  W_rq,  qrr, BT, 1024,  512);

    // rope + head assembly
    const int nqk = Bb * Tt * Hh * 32;
    assemble_qk<<<nqk / 256, 256>>>(kc, krr, Kh);
    assemble_qk<<<nqk / 256, 256>>>(qc, qrr, Qh);
    assemble_v<<<nqk / 256, 256>>>(v, Vh);

    // attention
    cudaFuncSetAttribute(attn_kernel, cudaFuncAttributeMaxDynamicSharedMemorySize,
                         ATTN_SMEM_BYTES);
    attn_kernel<<<dim3(Tt / 64, Bb * Hh), 256, ATTN_SMEM_BYTES>>>(Qh, Kh, Vh, attn);

    // output projection
    sgemm_tn<<<dim3(2048 / 128, BT / 128), 256>>>(attn, W_o, out, BT, 2048, 2048);
}

// round 6
// speedup vs baseline: 1.5896x; 1.5896x over previous
#include <cuda_runtime.h>
#include <cuda_bf16.h>
#include <stdint.h>
#include <math.h>

// ---------------------------------------------------------------------------
// MLA forward. GEMMs: bf16 split hi/lo on mma.sync (HMMA) tensor cores —
// plain sm_100 target (no 'a' features available in this toolchain).
// Attention: SIMT fp32 flash.
//   B=2, T=2048, C=2048, H=16, DH=128, L=512
//
// Fused layouts:
//   dproj [BT,2048] : cols 0-511 kv_d | 512-1023 q_d | 1024-2047 k_r(raw)
//   uk    [BT,3072] : cols 0-1023 k_c | 1024-3071 v
//   uq    [BT,2048] : cols 0-1023 q_c | 1024-2047 q_r(raw)
// Weight pool: P1=[W_kvD;W_qD;W_rk], P2=[W_kU;W_vU], P3=[W_qU;W_rq], PO=W_o
// ---------------------------------------------------------------------------

#define Bb 2
#define Tt 2048
#define Cc 2048
#define Hh 16
#define Dh 128
#define BT 4096   // B*T

// ---------------- fp32 scratch ----------------
__device__ float g_dproj[BT * 2048];
__device__ float g_uk   [BT * 3072];
__device__ float g_uq   [BT * 2048];
__device__ float g_Q    [BT * 2048];   // [B,H,T,128]
__device__ float g_K    [BT * 2048];
__device__ float g_V    [BT * 2048];
__device__ float g_attn [BT * 2048];   // [B,T,C]

// ---------------- bf16 split scratch ----------------
__device__ __nv_bfloat16 g_xh [BT * 2048];
__device__ __nv_bfloat16 g_xl [BT * 2048];
__device__ __nv_bfloat16 g_dph[BT * 2048];
__device__ __nv_bfloat16 g_dpl[BT * 2048];
__device__ __nv_bfloat16 g_ath[BT * 2048];
__device__ __nv_bfloat16 g_atl[BT * 2048];

// weight hi/lo pool (element offsets)
#define OFF_P1 0
#define OFF_P2 4194304
#define OFF_P3 5767168
#define OFF_PO 6815744
#define WTOT   11010048
__device__ __nv_bfloat16 g_wh[WTOT];
__device__ __nv_bfloat16 g_wl[WTOT];

// ===========================================================================
// helpers (base-target PTX only: cp.async, ldmatrix, mma.sync)
// ===========================================================================
__device__ __forceinline__ uint32_t smem_u32(const void* p) {
    uint32_t a;
    asm("{ .reg .u64 t; cvta.to.shared.u64 t, %1; cvt.u32.u64 %0, t; }"
        : "=r"(a) : "l"(p));
    return a;
}
__device__ __forceinline__ void cpasync16(uint32_t dst, const void* src) {
    asm volatile("cp.async.cg.shared.global [%0], [%1], 16;" :: "r"(dst), "l"(src));
}
#define CP_COMMIT() asm volatile("cp.async.commit_group;" ::: "memory")
template<int N> __device__ __forceinline__ void cp_wait() {
    asm volatile("cp.async.wait_group %0;" :: "n"(N) : "memory");
}
__device__ __forceinline__ void ldsm4(uint32_t* r, uint32_t addr) {
    asm volatile("ldmatrix.sync.aligned.m8n8.x4.shared.b16 {%0,%1,%2,%3}, [%4];"
        : "=r"(r[0]), "=r"(r[1]), "=r"(r[2]), "=r"(r[3]) : "r"(addr));
}
__device__ __forceinline__ void mma16816(float* d, const uint32_t* a, const uint32_t* b) {
    asm volatile("mma.sync.aligned.m16n8k16.row.col.f32.bf16.bf16.f32 "
        "{%0,%1,%2,%3}, {%4,%5,%6,%7}, {%8,%9}, {%0,%1,%2,%3};"
        : "+f"(d[0]), "+f"(d[1]), "+f"(d[2]), "+f"(d[3])
        : "r"(a[0]), "r"(a[1]), "r"(a[2]), "r"(a[3]), "r"(b[0]), "r"(b[1]));
}

// ===========================================================================
// fp32 -> bf16 hi/lo split
// ===========================================================================
__global__ void __launch_bounds__(256)
split_bf16(const float* __restrict__ in, __nv_bfloat16* __restrict__ hi,
           __nv_bfloat16* __restrict__ lo, int n)
{
    int i = (blockIdx.x * 256 + threadIdx.x) * 4;
    if (i >= n) return;
    float4 v = *(const float4*)&in[i];
    __nv_bfloat16 h0 = __float2bfloat16(v.x);
    __nv_bfloat16 h1 = __float2bfloat16(v.y);
    __nv_bfloat16 h2 = __float2bfloat16(v.z);
    __nv_bfloat16 h3 = __float2bfloat16(v.w);
    __nv_bfloat16 l0 = __float2bfloat16(v.x - __bfloat162float(h0));
    __nv_bfloat16 l1 = __float2bfloat16(v.y - __bfloat162float(h1));
    __nv_bfloat16 l2 = __float2bfloat16(v.z - __bfloat162float(h2));
    __nv_bfloat16 l3 = __float2bfloat16(v.w - __bfloat162float(h3));
    __nv_bfloat162 ph0 = __halves2bfloat162(h0, h1);
    __nv_bfloat162 ph1 = __halves2bfloat162(h2, h3);
    __nv_bfloat162 pl0 = __halves2bfloat162(l0, l1);
    __nv_bfloat162 pl1 = __halves2bfloat162(l2, l3);
    *(uint2*)&hi[i] = make_uint2(*(uint32_t*)&ph0, *(uint32_t*)&ph1);
    *(uint2*)&lo[i] = make_uint2(*(uint32_t*)&pl0, *(uint32_t*)&pl1);
}

// ===========================================================================
// mma.sync bf16 split-GEMM:  C[M,N] = A[M,K] @ W[N,K]^T
//   = Ah*Wh + Ah*Wl + Al*Wh  (fp32 accumulators)
// CTA tile 128x128x32, 8 warps (2x4), warp tile 64x32.
// smem pitch 40 bf16 (80B): conflict-free ldmatrix, 16B-aligned cp.async.
// 2-stage cp.async double buffer.
// ===========================================================================
#define Pp 40
#define TILE_B (128 * Pp * 2)      // 10240 bytes per tile
#define STG_B  (4 * TILE_B)        // 40960 bytes per stage (AH, AL, WH, WL)
#define GEMM_SMEM (2 * STG_B)      // 81920

__global__ void __launch_bounds__(256)
bgemm_tn(const __nv_bfloat16* __restrict__ Ah_, const __nv_bfloat16* __restrict__ Al_,
         int lda,
         const __nv_bfloat16* __restrict__ Wh_, const __nv_bfloat16* __restrict__ Wl_,
         float* __restrict__ C, int ldc, int M, int N, int K)
{
    extern __shared__ char smem[];
    const uint32_t sb = smem_u32(smem);
    const int tid = threadIdx.x;
    const int lid = tid & 31;
    const int wid = tid >> 5;
    const int m0 = blockIdx.y * 128;
    const int n0 = blockIdx.x * 128;
    const int wm = (wid & 1) * 64;     // warp M offset
    const int wn = (wid >> 1) * 32;    // warp N offset

    float acc[4][4][4];
#pragma unroll
    for (int i = 0; i < 4; i++)
#pragma unroll
        for (int j = 0; j < 4; j++)
#pragma unroll
            for (int q = 0; q < 4; q++) acc[i][j][q] = 0.f;

    auto fill = [&](int stage, int k0) {
        const uint32_t s0 = sb + stage * STG_B;
#pragma unroll
        for (int it = 0; it < 2; it++) {
            const int idx = tid + it * 256;         // 0..511
            const int row = idx >> 2;               // 0..127
            const int ch  = idx & 3;                // 16B chunk
            const uint32_t so = (uint32_t)(row * Pp + ch * 8) * 2;
            const size_t ga = (size_t)(m0 + row) * lda + k0 + ch * 8;
            const size_t gw = (size_t)(n0 + row) * K   + k0 + ch * 8;
            cpasync16(s0 + so,              Ah_ + ga);
            cpasync16(s0 + TILE_B + so,     Al_ + ga);
            cpasync16(s0 + 2 * TILE_B + so, Wh_ + gw);
            cpasync16(s0 + 3 * TILE_B + so, Wl_ + gw);
        }
    };

    const int nk = K / 32;
    fill(0, 0); CP_COMMIT();

    for (int kt = 0; kt < nk; kt++) {
        const int cur = kt & 1;
        if (kt + 1 < nk) { fill(cur ^ 1, (kt + 1) * 32); CP_COMMIT(); cp_wait<1>(); }
        else             { cp_wait<0>(); }
        __syncthreads();

        const uint32_t s0 = sb + cur * STG_B;
#pragma unroll
        for (int ks = 0; ks < 2; ks++) {
            uint32_t aH[4][4], aL[4][4], bH[2][4], bL[2][4];
#pragma unroll
            for (int mi = 0; mi < 4; mi++) {
                const uint32_t ad = s0 +
                    (uint32_t)(((wm + mi * 16 + (lid & 15)) * Pp + ks * 16 + (lid >> 4) * 8) * 2);
                ldsm4(aH[mi], ad);
                ldsm4(aL[mi], ad + TILE_B);
            }
#pragma unroll
            for (int j = 0; j < 2; j++) {
                const int g = lid >> 3;
                const int nrow = wn + j * 16 + (lid & 7) + ((g >> 1) << 3);
                const int col  = ks * 16 + (g & 1) * 8;
                const uint32_t bd = s0 + 2 * TILE_B + (uint32_t)((nrow * Pp + col) * 2);
                ldsm4(bH[j], bd);
                ldsm4(bL[j], bd + TILE_B);
            }
#pragma unroll
            for (int mi = 0; mi < 4; mi++)
#pragma unroll
                for (int nj = 0; nj < 4; nj++) {
                    const uint32_t* bh = &bH[nj >> 1][(nj & 1) * 2];
                    const uint32_t* bl = &bL[nj >> 1][(nj & 1) * 2];
                    mma16816(acc[mi][nj], aH[mi], bh);
                    mma16816(acc[mi][nj], aH[mi], bl);
                    mma16816(acc[mi][nj], aL[mi], bh);
                }
        }
        __syncthreads();
    }

    // ---- epilogue: c frag rows = l>>2 (+8), cols = (l&3)*2 ----
#pragma unroll
    for (int mi = 0; mi < 4; mi++)
#pragma unroll
        for (int nj = 0; nj < 4; nj++) {
            const int r0 = m0 + wm + mi * 16 + (lid >> 2);
            const int c0 = n0 + wn + nj * 8 + (lid & 3) * 2;
            *(float2*)&C[(size_t)r0 * ldc + c0] =
                make_float2(acc[mi][nj][0], acc[mi][nj][1]);
            *(float2*)&C[(size_t)(r0 + 8) * ldc + c0] =
                make_float2(acc[mi][nj][2], acc[mi][nj][3]);
        }
}

// ===========================================================================
// RoPE + head assembly (stride-parameterized for fused buffers)
// ===========================================================================
__global__ void __launch_bounds__(256)
assemble_qk(const float* __restrict__ cpart, int cs,
            const float* __restrict__ rraw, int rs,
            float* __restrict__ outp)
{
    const int idx = blockIdx.x * blockDim.x + threadIdx.x; // B*T*H*32
    const int p = idx & 31;
    const int h = (idx >> 5) & (Hh - 1);
    const int t = (idx >> 9) & (Tt - 1);
    const int b = idx >> 20;

    const size_t crow = (size_t)(b * Tt + t) * cs + (h << 6);
    const size_t rrow = (size_t)(b * Tt + t) * rs + (h << 6);
    const int ob = (((b * Hh + h) * Tt + t) << 7);

    float2 cv = *(const float2*)&cpart[crow + 2 * p];
    *(float2*)&outp[ob + 2 * p] = cv;

    float2 rv = *(const float2*)&rraw[rrow + 2 * p];
    const int j0 = (h << 6) + 2 * p;
    const float kfc = -0.00899447225546836f;   // -ln(10000)/1024
    float freq = expf((float)j0 * kfc);
    float ang  = (float)t * freq;
    float s, c;
    sincosf(ang, &s, &c);
    float2 o;
    o.x = rv.x * c - rv.y * s;
    o.y = rv.y * c + rv.x * s;
    *(float2*)&outp[ob + 64 + 2 * p] = o;
}

// V transpose: V[b,h,t,d] = vin[(b*T+t)*vs + h*128 + d]
__global__ void __launch_bounds__(256)
assemble_v(const float* __restrict__ vin, int vs, float* __restrict__ vout)
{
    const int idx = blockIdx.x * blockDim.x + threadIdx.x; // B*H*T*32
    const int d4 = idx & 31;
    const int t  = (idx >> 5) & (Tt - 1);
    const int h  = (idx >> 16) & (Hh - 1);
    const int b  = idx >> 20;
    float4 v = *(const float4*)&vin[(size_t)(b * Tt + t) * vs + h * Dh + d4 * 4];
    *(float4*)&vout[(size_t)idx * 4] = v;
}

// ===========================================================================
// Causal flash attention, fp32 SIMT
// ===========================================================================
#define ATTN_SMEM_FLOATS (3 * 64 * 132 + 64 * 65 + 3 * 64)
#define ATTN_SMEM_BYTES  (ATTN_SMEM_FLOATS * 4)

__global__ void __launch_bounds__(256)
attn_kernel(const float* __restrict__ Q, const float* __restrict__ K,
            const float* __restrict__ V, float* __restrict__ Aout)
{
    extern __shared__ float smemf[];
    float* Qs = smemf;
    float* Ks = Qs + 64 * 132;
    float* Vs = Ks + 64 * 132;
    float* Ss = Vs + 64 * 132;
    float* sM = Ss + 64 * 65;
    float* sL = sM + 64;
    float* sA = sL + 64;

    const int qt  = gridDim.x - 1 - blockIdx.x;
    const int bh  = blockIdx.y;
    const int tid = threadIdx.x;
    const int tx  = tid & 15;
    const int ty  = tid >> 4;
    const float scale = 0.08838834764831845f;

    const float* Qg = Q + ((size_t)bh * Tt + qt * 64) * Dh;
    const float* Kg = K + (size_t)bh * Tt * Dh;
    const float* Vg = V + (size_t)bh * Tt * Dh;

    for (int i = tid; i < 64 * 32; i += 256) {
        const int r = i >> 5, d4 = i & 31;
        *(float4*)&Qs[r * 132 + d4 * 4] = *(const float4*)&Qg[r * Dh + d4 * 4];
    }
    if (tid < 64) { sM[tid] = -1e30f; sL[tid] = 0.f; }

    float o[4][8];
#pragma unroll
    for (int i = 0; i < 4; i++)
#pragma unroll
        for (int j = 0; j < 8; j++) o[i][j] = 0.f;

    __syncthreads();

    const int ntiles = qt + 1;
    for (int kt = 0; kt < ntiles; kt++) {
        for (int i = tid; i < 64 * 32; i += 256) {
            const int r = i >> 5, d4 = i & 31;
            *(float4*)&Ks[r * 132 + d4 * 4] =
                *(const float4*)&Kg[(kt * 64 + r) * Dh + d4 * 4];
            *(float4*)&Vs[r * 132 + d4 * 4] =
                *(const float4*)&Vg[(kt * 64 + r) * Dh + d4 * 4];
        }
        __syncthreads();

        float acc[4][4];
#pragma unroll
        for (int i = 0; i < 4; i++)
#pragma unroll
            for (int j = 0; j < 4; j++) acc[i][j] = 0.f;

        for (int d4 = 0; d4 < 32; d4++) {
            float4 qf[4], kf[4];
#pragma unroll
            for (int i = 0; i < 4; i++)
                qf[i] = *(const float4*)&Qs[(4 * ty + i) * 132 + d4 * 4];
#pragma unroll
            for (int j = 0; j < 4; j++)
                kf[j] = *(const float4*)&Ks[(tx + 16 * j) * 132 + d4 * 4];
#pragma unroll
            for (int i = 0; i < 4; i++)
#pragma unroll
                for (int j = 0; j < 4; j++) {
                    acc[i][j] += qf[i].x * kf[j].x;
                    acc[i][j] += qf[i].y * kf[j].y;
                    acc[i][j] += qf[i].z * kf[j].z;
                    acc[i][j] += qf[i].w * kf[j].w;
                }
        }

#pragma unroll
        for (int i = 0; i < 4; i++) {
            const int r  = 4 * ty + i;
            const int qg = qt * 64 + r;
#pragma unroll
            for (int j = 0; j < 4; j++) {
                const int c  = tx + 16 * j;
                const int sg = kt * 64 + c;
                Ss[r * 65 + c] = (sg <= qg) ? acc[i][j] * scale : -1e30f;
            }
        }
        __syncthreads();

        {
            const int r  = tid >> 2;
            const int qd = tid & 3;
            float tmax = -1e30f;
#pragma unroll
            for (int c0 = 0; c0 < 16; c0++)
                tmax = fmaxf(tmax, Ss[r * 65 + qd * 16 + c0]);
            tmax = fmaxf(tmax, __shfl_xor_sync(0xffffffffu, tmax, 1));
            tmax = fmaxf(tmax, __shfl_xor_sync(0xffffffffu, tmax, 2));

            const float m_old = sM[r];
            const float m_new = fmaxf(m_old, tmax);
            float psum = 0.f;
#pragma unroll
            for (int c0 = 0; c0 < 16; c0++) {
                float p = expf(Ss[r * 65 + qd * 16 + c0] - m_new);
                Ss[r * 65 + qd * 16 + c0] = p;
                psum += p;
            }
            psum += __shfl_xor_sync(0xffffffffu, psum, 1);
            psum += __shfl_xor_sync(0xffffffffu, psum, 2);
            if (qd == 0) {
                const float alpha = expf(m_old - m_new);
                sA[r] = alpha;
                sM[r] = m_new;
                sL[r] = sL[r] * alpha + psum;
            }
        }
        __syncthreads();

#pragma unroll
        for (int i = 0; i < 4; i++) {
            const float al = sA[4 * ty + i];
#pragma unroll
            for (int j = 0; j < 8; j++) o[i][j] *= al;
        }
        for (int c = 0; c < 64; c++) {
            float p[4];
#pragma unroll
            for (int i = 0; i < 4; i++) p[i] = Ss[(4 * ty + i) * 65 + c];
            float4 v0 = *(const float4*)&Vs[c * 132 + 4 * tx];
            float4 v1 = *(const float4*)&Vs[c * 132 + 64 + 4 * tx];
#pragma unroll
            for (int i = 0; i < 4; i++) {
                o[i][0] += p[i] * v0.x;  o[i][1] += p[i] * v0.y;
                o[i][2] += p[i] * v0.z;  o[i][3] += p[i] * v0.w;
                o[i][4] += p[i] * v1.x;  o[i][5] += p[i] * v1.y;
                o[i][6] += p[i] * v1.z;  o[i][7] += p[i] * v1.w;
            }
        }
        __syncthreads();
    }

    const int b = bh >> 4;
    const int h = bh & 15;
#pragma unroll
    for (int i = 0; i < 4; i++) {
        const int r = 4 * ty + i;
        const float inv = 1.f / sL[r];
        const int t = qt * 64 + r;
        float* dst = Aout + (size_t)(b * Tt + t) * Cc + h * Dh;
        float4 v0 = make_float4(o[i][0] * inv, o[i][1] * inv,
                                o[i][2] * inv, o[i][3] * inv);
        float4 v1 = make_float4(o[i][4] * inv, o[i][5] * inv,
                                o[i][6] * inv, o[i][7] * inv);
        *(float4*)&dst[4 * tx]      = v0;
        *(float4*)&dst[64 + 4 * tx] = v1;
    }
}

// ===========================================================================
// host launch
// ===========================================================================
static inline void split(const float* in, __nv_bfloat16* hi, __nv_bfloat16* lo, int n) {
    split_bf16<<<n / 1024, 256>>>(in, hi, lo, n);
}

extern "C" void kernel_launch(void* const* d_in, const int* in_sizes, int n_in,
                              void* d_out, int out_size)
{
    const float* x     = (const float*)d_in[0];
    const float* W_kvD = (const float*)d_in[1];
    const float* W_qD  = (const float*)d_in[2];
    const float* W_kU  = (const float*)d_in[3];
    const float* W_vU  = (const float*)d_in[4];
    const float* W_qU  = (const float*)d_in[5];
    const float* W_rk  = (const float*)d_in[6];
    const float* W_rq  = (const float*)d_in[7];
    const float* W_o   = (const float*)d_in[8];
    float* out = (float*)d_out;

    float *dproj, *uk, *uq, *Qh, *Kh, *Vh, *attn;
    cudaGetSymbolAddress((void**)&dproj, g_dproj);
    cudaGetSymbolAddress((void**)&uk,    g_uk);
    cudaGetSymbolAddress((void**)&uq,    g_uq);
    cudaGetSymbolAddress((void**)&Qh,    g_Q);
    cudaGetSymbolAddress((void**)&Kh,    g_K);
    cudaGetSymbolAddress((void**)&Vh,    g_V);
    cudaGetSymbolAddress((void**)&attn,  g_attn);

    __nv_bfloat16 *xh, *xl, *dph, *dpl, *ath, *atl, *wh, *wl;
    cudaGetSymbolAddress((void**)&xh,  g_xh);
    cudaGetSymbolAddress((void**)&xl,  g_xl);
    cudaGetSymbolAddress((void**)&dph, g_dph);
    cudaGetSymbolAddress((void**)&dpl, g_dpl);
    cudaGetSymbolAddress((void**)&ath, g_ath);
    cudaGetSymbolAddress((void**)&atl, g_atl);
    cudaGetSymbolAddress((void**)&wh,  g_wh);
    cudaGetSymbolAddress((void**)&wl,  g_wl);

    cudaFuncSetAttribute(bgemm_tn, cudaFuncAttributeMaxDynamicSharedMemorySize, GEMM_SMEM);
    cudaFuncSetAttribute(attn_kernel, cudaFuncAttributeMaxDynamicSharedMemorySize,
                         ATTN_SMEM_BYTES);

    // ---- split inputs to bf16 hi/lo (weights into fused pools) ----
    split(x,     xh, xl, BT * 2048);
    split(W_kvD, wh + OFF_P1,               wl + OFF_P1,                512 * 2048);
    split(W_qD,  wh + OFF_P1 +  512 * 2048, wl + OFF_P1 +  512 * 2048,  512 * 2048);
    split(W_rk,  wh + OFF_P1 + 1024 * 2048, wl + OFF_P1 + 1024 * 2048, 1024 * 2048);
    split(W_kU,  wh + OFF_P2,               wl + OFF_P2,               1024 * 512);
    split(W_vU,  wh + OFF_P2 + 1024 * 512,  wl + OFF_P2 + 1024 * 512,  2048 * 512);
    split(W_qU,  wh + OFF_P3,               wl + OFF_P3,               1024 * 512);
    split(W_rq,  wh + OFF_P3 + 1024 * 512,  wl + OFF_P3 + 1024 * 512,  1024 * 512);
    split(W_o,   wh + OFF_PO,               wl + OFF_PO,               2048 * 2048);

    // ---- fused down projection: dproj = x @ [W_kvD;W_qD;W_rk]^T ----
    bgemm_tn<<<dim3(16, 32), 256, GEMM_SMEM>>>(xh, xl, 2048,
        wh + OFF_P1, wl + OFF_P1, dproj, 2048, BT, 2048, 2048);

    split(dproj, dph, dpl, BT * 2048);

    // ---- fused up projections ----
    bgemm_tn<<<dim3(24, 32), 256, GEMM_SMEM>>>(dph, dpl, 2048,
        wh + OFF_P2, wl + OFF_P2, uk, 3072, BT, 3072, 512);
    bgemm_tn<<<dim3(16, 32), 256, GEMM_SMEM>>>(dph + 512, dpl + 512, 2048,
        wh + OFF_P3, wl + OFF_P3, uq, 2048, BT, 2048, 512);

    // ---- rope + head assembly ----
    const int nqk = Bb * Tt * Hh * 32;
    assemble_qk<<<nqk / 256, 256>>>(uk, 3072, dproj + 1024, 2048, Kh);   // k_c | rope(k_r)
    assemble_qk<<<nqk / 256, 256>>>(uq, 2048, uq + 1024,    2048, Qh);   // q_c | rope(q_r)
    assemble_v <<<nqk / 256, 256>>>(uk + 1024, 3072, Vh);

    // ---- attention ----
    attn_kernel<<<dim3(Tt / 64, Bb * Hh), 256, ATTN_SMEM_BYTES>>>(Qh, Kh, Vh, attn);

    // ---- output projection ----
    split(attn, ath, atl, BT * 2048);
    bgemm_tn<<<dim3(16, 32), 256, GEMM_SMEM>>>(ath, atl, 2048,
        wh + OFF_PO, wl + OFF_PO, out, 2048, BT, 2048, 2048);
}

// round 8
// speedup vs baseline: 3.2033x; 2.0152x over previous
#include <cuda_runtime.h>
#include <cuda_bf16.h>
#include <cuda_fp16.h>
#include <stdint.h>
#include <math.h>

// ---------------------------------------------------------------------------
// MLA forward.
//   GEMMs: bf16 split hi/lo on mma.sync HMMA (3-product, fp32-grade).
//   Attention: fp16 single-product HMMA flash attention (fp32 softmax/accum).
//   B=2, T=2048, C=2048, H=16, DH=128, L=512
//
// Fused layouts:
//   dproj [BT,2048] : cols 0-511 kv_d | 512-1023 q_d | 1024-2047 k_r(raw)
//   uk    [BT,3072] : cols 0-1023 k_c | 1024-3071 v
//   uq    [BT,2048] : cols 0-1023 q_c | 1024-2047 q_r(raw)
// Weight pool: P1=[W_kvD;W_qD;W_rk], P2=[W_kU;W_vU], P3=[W_qU;W_rq], PO=W_o
// ---------------------------------------------------------------------------

#define Bb 2
#define Tt 2048
#define Cc 2048
#define Hh 16
#define Dh 128
#define BT 4096   // B*T

// ---------------- fp32 scratch ----------------
__device__ float g_dproj[BT * 2048];
__device__ float g_uk   [BT * 3072];
__device__ float g_uq   [BT * 2048];

// ---------------- bf16 split scratch ----------------
__device__ __nv_bfloat16 g_xh [BT * 2048];
__device__ __nv_bfloat16 g_xl [BT * 2048];
__device__ __nv_bfloat16 g_dph[BT * 2048];
__device__ __nv_bfloat16 g_dpl[BT * 2048];
__device__ __nv_bfloat16 g_ath[BT * 2048];
__device__ __nv_bfloat16 g_atl[BT * 2048];

// ---------------- fp16 attention operands [B,H,T,128] ----------------
__device__ __half g_Q16[BT * 2048];
__device__ __half g_K16[BT * 2048];
__device__ __half g_V16[BT * 2048];

// weight hi/lo pool (element offsets)
#define OFF_P1 0
#define OFF_P2 4194304
#define OFF_P3 5767168
#define OFF_PO 6815744
#define WTOT   11010048
__device__ __nv_bfloat16 g_wh[WTOT];
__device__ __nv_bfloat16 g_wl[WTOT];

// ===========================================================================
// helpers (base-target PTX only: cp.async, ldmatrix, mma.sync)
// ===========================================================================
__device__ __forceinline__ uint32_t smem_u32(const void* p) {
    uint32_t a;
    asm("{ .reg .u64 t; cvta.to.shared.u64 t, %1; cvt.u32.u64 %0, t; }"
        : "=r"(a) : "l"(p));
    return a;
}
__device__ __forceinline__ void cpasync16(uint32_t dst, const void* src) {
    asm volatile("cp.async.cg.shared.global [%0], [%1], 16;" :: "r"(dst), "l"(src));
}
#define CP_COMMIT() asm volatile("cp.async.commit_group;" ::: "memory")
template<int N> __device__ __forceinline__ void cp_wait() {
    asm volatile("cp.async.wait_group %0;" :: "n"(N) : "memory");
}
__device__ __forceinline__ void ldsm4(uint32_t* r, uint32_t addr) {
    asm volatile("ldmatrix.sync.aligned.m8n8.x4.shared.b16 {%0,%1,%2,%3}, [%4];"
        : "=r"(r[0]), "=r"(r[1]), "=r"(r[2]), "=r"(r[3]) : "r"(addr));
}
__device__ __forceinline__ void ldsm4t(uint32_t* r, uint32_t addr) {
    asm volatile("ldmatrix.sync.aligned.m8n8.x4.trans.shared.b16 {%0,%1,%2,%3}, [%4];"
        : "=r"(r[0]), "=r"(r[1]), "=r"(r[2]), "=r"(r[3]) : "r"(addr));
}
__device__ __forceinline__ void mma16816(float* d, const uint32_t* a, const uint32_t* b) {
    asm volatile("mma.sync.aligned.m16n8k16.row.col.f32.bf16.bf16.f32 "
        "{%0,%1,%2,%3}, {%4,%5,%6,%7}, {%8,%9}, {%0,%1,%2,%3};"
        : "+f"(d[0]), "+f"(d[1]), "+f"(d[2]), "+f"(d[3])
        : "r"(a[0]), "r"(a[1]), "r"(a[2]), "r"(a[3]), "r"(b[0]), "r"(b[1]));
}
__device__ __forceinline__ void mma16816h(float* d, const uint32_t* a, const uint32_t* b) {
    asm volatile("mma.sync.aligned.m16n8k16.row.col.f32.f16.f16.f32 "
        "{%0,%1,%2,%3}, {%4,%5,%6,%7}, {%8,%9}, {%0,%1,%2,%3};"
        : "+f"(d[0]), "+f"(d[1]), "+f"(d[2]), "+f"(d[3])
        : "r"(a[0]), "r"(a[1]), "r"(a[2]), "r"(a[3]), "r"(b[0]), "r"(b[1]));
}
__device__ __forceinline__ uint32_t pack_h2(float a, float b) {
    __half2 h = __floats2half2_rn(a, b);
    return *(uint32_t*)&h;
}
__device__ __forceinline__ void hilo_bf2(float a, float b, uint32_t& hi, uint32_t& lo) {
    __nv_bfloat16 h0 = __float2bfloat16(a);
    __nv_bfloat16 h1 = __float2bfloat16(b);
    __nv_bfloat16 l0 = __float2bfloat16(a - __bfloat162float(h0));
    __nv_bfloat16 l1 = __float2bfloat16(b - __bfloat162float(h1));
    __nv_bfloat162 hv = __halves2bfloat162(h0, h1);
    __nv_bfloat162 lv = __halves2bfloat162(l0, l1);
    hi = *(uint32_t*)&hv;
    lo = *(uint32_t*)&lv;
}

// ===========================================================================
// fp32 -> bf16 hi/lo split
// ===========================================================================
__global__ void __launch_bounds__(256)
split_bf16(const float* __restrict__ in, __nv_bfloat16* __restrict__ hi,
           __nv_bfloat16* __restrict__ lo, int n)
{
    int i = (blockIdx.x * 256 + threadIdx.x) * 4;
    if (i >= n) return;
    float4 v = *(const float4*)&in[i];
    uint32_t h0, l0, h1, l1;
    hilo_bf2(v.x, v.y, h0, l0);
    hilo_bf2(v.z, v.w, h1, l1);
    *(uint2*)&hi[i] = make_uint2(h0, h1);
    *(uint2*)&lo[i] = make_uint2(l0, l1);
}

// ===========================================================================
// mma.sync bf16 split-GEMM:  C[M,N] = A[M,K] @ W[N,K]^T
// CTA tile 128x128x32, 8 warps (2x4), warp tile 64x32.
// smem pitch 40 bf16; 2-stage cp.async double buffer.
// ===========================================================================
#define Pp 40
#define TILE_B (128 * Pp * 2)
#define STG_B  (4 * TILE_B)
#define GEMM_SMEM (2 * STG_B)      // 81920

__global__ void __launch_bounds__(256)
bgemm_tn(const __nv_bfloat16* __restrict__ Ah_, const __nv_bfloat16* __restrict__ Al_,
         int lda,
         const __nv_bfloat16* __restrict__ Wh_, const __nv_bfloat16* __restrict__ Wl_,
         float* __restrict__ C, int ldc, int M, int N, int K)
{
    extern __shared__ char smem[];
    const uint32_t sb = smem_u32(smem);
    const int tid = threadIdx.x;
    const int lid = tid & 31;
    const int wid = tid >> 5;
    const int m0 = blockIdx.y * 128;
    const int n0 = blockIdx.x * 128;
    const int wm = (wid & 1) * 64;
    const int wn = (wid >> 1) * 32;

    float acc[4][4][4];
#pragma unroll
    for (int i = 0; i < 4; i++)
#pragma unroll
        for (int j = 0; j < 4; j++)
#pragma unroll
            for (int q = 0; q < 4; q++) acc[i][j][q] = 0.f;

    auto fill = [&](int stage, int k0) {
        const uint32_t s0 = sb + stage * STG_B;
#pragma unroll
        for (int it = 0; it < 2; it++) {
            const int idx = tid + it * 256;
            const int row = idx >> 2;
            const int ch  = idx & 3;
            const uint32_t so = (uint32_t)(row * Pp + ch * 8) * 2;
            const size_t ga = (size_t)(m0 + row) * lda + k0 + ch * 8;
            const size_t gw = (size_t)(n0 + row) * K   + k0 + ch * 8;
            cpasync16(s0 + so,              Ah_ + ga);
            cpasync16(s0 + TILE_B + so,     Al_ + ga);
            cpasync16(s0 + 2 * TILE_B + so, Wh_ + gw);
            cpasync16(s0 + 3 * TILE_B + so, Wl_ + gw);
        }
    };

    const int nk = K / 32;
    fill(0, 0); CP_COMMIT();

    for (int kt = 0; kt < nk; kt++) {
        const int cur = kt & 1;
        if (kt + 1 < nk) { fill(cur ^ 1, (kt + 1) * 32); CP_COMMIT(); cp_wait<1>(); }
        else             { cp_wait<0>(); }
        __syncthreads();

        const uint32_t s0 = sb + cur * STG_B;
#pragma unroll
        for (int ks = 0; ks < 2; ks++) {
            uint32_t aH[4][4], aL[4][4], bH[2][4], bL[2][4];
#pragma unroll
            for (int mi = 0; mi < 4; mi++) {
                const uint32_t ad = s0 +
                    (uint32_t)(((wm + mi * 16 + (lid & 15)) * Pp + ks * 16 + (lid >> 4) * 8) * 2);
                ldsm4(aH[mi], ad);
                ldsm4(aL[mi], ad + TILE_B);
            }
#pragma unroll
            for (int j = 0; j < 2; j++) {
                const int g = lid >> 3;
                const int nrow = wn + j * 16 + (lid & 7) + ((g >> 1) << 3);
                const int col  = ks * 16 + (g & 1) * 8;
                const uint32_t bd = s0 + 2 * TILE_B + (uint32_t)((nrow * Pp + col) * 2);
                ldsm4(bH[j], bd);
                ldsm4(bL[j], bd + TILE_B);
            }
#pragma unroll
            for (int mi = 0; mi < 4; mi++)
#pragma unroll
                for (int nj = 0; nj < 4; nj++) {
                    const uint32_t* bh = &bH[nj >> 1][(nj & 1) * 2];
                    const uint32_t* bl = &bL[nj >> 1][(nj & 1) * 2];
                    mma16816(acc[mi][nj], aH[mi], bh);
                    mma16816(acc[mi][nj], aH[mi], bl);
                    mma16816(acc[mi][nj], aL[mi], bh);
                }
        }
        __syncthreads();
    }

#pragma unroll
    for (int mi = 0; mi < 4; mi++)
#pragma unroll
        for (int nj = 0; nj < 4; nj++) {
            const int r0 = m0 + wm + mi * 16 + (lid >> 2);
            const int c0 = n0 + wn + nj * 8 + (lid & 3) * 2;
            *(float2*)&C[(size_t)r0 * ldc + c0] =
                make_float2(acc[mi][nj][0], acc[mi][nj][1]);
            *(float2*)&C[(size_t)(r0 + 8) * ldc + c0] =
                make_float2(acc[mi][nj][2], acc[mi][nj][3]);
        }
}

// ===========================================================================
// RoPE + head assembly -> fp16 [B,H,T,128]
// ===========================================================================
__global__ void __launch_bounds__(256)
assemble_qk_h(const float* __restrict__ cpart, int cs,
              const float* __restrict__ rraw, int rs,
              __half* __restrict__ outp)
{
    const int idx = blockIdx.x * blockDim.x + threadIdx.x; // B*T*H*32
    const int p = idx & 31;
    const int h = (idx >> 5) & (Hh - 1);
    const int t = (idx >> 9) & (Tt - 1);
    const int b = idx >> 20;

    const size_t crow = (size_t)(b * Tt + t) * cs + (h << 6);
    const size_t rrow = (size_t)(b * Tt + t) * rs + (h << 6);
    const size_t ob = ((size_t)((b * Hh + h) * Tt + t) << 7);

    float2 cv = *(const float2*)&cpart[crow + 2 * p];
    *(uint32_t*)&outp[ob + 2 * p] = pack_h2(cv.x, cv.y);

    float2 rv = *(const float2*)&rraw[rrow + 2 * p];
    const int j0 = (h << 6) + 2 * p;
    const float kfc = -0.00899447225546836f;   // -ln(10000)/1024
    float freq = expf((float)j0 * kfc);
    float ang  = (float)t * freq;
    float s, c;
    sincosf(ang, &s, &c);
    *(uint32_t*)&outp[ob + 64 + 2 * p] =
        pack_h2(rv.x * c - rv.y * s, rv.y * c + rv.x * s);
}

__global__ void __launch_bounds__(256)
assemble_v_h(const float* __restrict__ vin, int vs, __half* __restrict__ vout)
{
    const int idx = blockIdx.x * blockDim.x + threadIdx.x; // B*H*T*32
    const int d4 = idx & 31;
    const int t  = (idx >> 5) & (Tt - 1);
    const int h  = (idx >> 16) & (Hh - 1);
    const int b  = idx >> 20;
    float4 v = *(const float4*)&vin[(size_t)(b * Tt + t) * vs + h * Dh + d4 * 4];
    *(uint2*)&vout[(size_t)idx * 4] =
        make_uint2(pack_h2(v.x, v.y), pack_h2(v.z, v.w));
}

// ===========================================================================
// fp16 tensor-core causal flash attention.
//   BQ=128 (8 warps x 16 rows), BKV=64, D=128. fp32 softmax + accumulators.
//   Double-buffered cp.async K/V. Output written as bf16 hi/lo for W_o GEMM.
// ===========================================================================
#define ATP 136
#define AQ_B   (128 * ATP * 2)         // 34816
#define KV_TILE (64 * ATP * 2)         // 17408
#define KV_STG  (2 * KV_TILE)          // 34816
#define ATTN2_SMEM (AQ_B + 2 * KV_STG) // 104448

__global__ void __launch_bounds__(256)
attn_tc(const __half* __restrict__ Qg, const __half* __restrict__ Kg,
        const __half* __restrict__ Vg,
        __nv_bfloat16* __restrict__ OH, __nv_bfloat16* __restrict__ OL)
{
    extern __shared__ char sm2[];
    const uint32_t sb = smem_u32(sm2);
    const int tid = threadIdx.x;
    const int lid = tid & 31;
    const int wid = tid >> 5;
    const int qt = gridDim.x - 1 - blockIdx.x;   // longest first
    const int bh = blockIdx.y;
    const int b = bh >> 4, h = bh & 15;
    const size_t gq = ((size_t)bh * Tt + qt * 128) * 128;
    const size_t gk = (size_t)bh * Tt * 128;

    // Q fill (one-shot)
#pragma unroll
    for (int it = 0; it < 8; it++) {
        const int idx = tid + it * 256;
        const int row = idx >> 4, ch = idx & 15;
        cpasync16(sb + row * (ATP * 2) + ch * 16, Qg + gq + row * 128 + ch * 8);
    }
    CP_COMMIT();

    auto fillKV = [&](int stg, int kt) {
        const uint32_t s0 = sb + AQ_B + stg * KV_STG;
        const size_t g0 = gk + (size_t)kt * 64 * 128;
#pragma unroll
        for (int it = 0; it < 4; it++) {
            const int idx = tid + it * 256;
            const int row = idx >> 4, ch = idx & 15;
            const uint32_t d = s0 + row * (ATP * 2) + ch * 16;
            cpasync16(d,           Kg + g0 + row * 128 + ch * 8);
            cpasync16(d + KV_TILE, Vg + g0 + row * 128 + ch * 8);
        }
    };

    float o[16][4];
#pragma unroll
    for (int i = 0; i < 16; i++)
#pragma unroll
        for (int q = 0; q < 4; q++) o[i][q] = 0.f;
    float mr0 = -1e30f, mr1 = -1e30f, lr0 = 0.f, lr1 = 0.f;
    const int qr0 = qt * 128 + wid * 16;
    const float CL = 0.12751149355487718f;  // (1/sqrt(128))*log2(e)

    const int ktmax = 2 * qt + 1;
    fillKV(0, 0); CP_COMMIT();

    for (int kt = 0; kt <= ktmax; kt++) {
        if (kt < ktmax) { fillKV((kt + 1) & 1, kt + 1); CP_COMMIT(); cp_wait<1>(); }
        else            { cp_wait<0>(); }
        __syncthreads();

        if (kt * 64 <= qr0 + 15) {   // warp has at least one valid (q,k) pair
            const uint32_t s0 = sb + AQ_B + (kt & 1) * KV_STG;

            // ---- S = Q K^T ------------------------------------------------
            float sc[8][4];
#pragma unroll
            for (int i = 0; i < 8; i++)
#pragma unroll
                for (int q = 0; q < 4; q++) sc[i][q] = 0.f;

#pragma unroll
            for (int ks = 0; ks < 8; ks++) {
                uint32_t qa[4];
                ldsm4(qa, sb + (uint32_t)(((wid * 16 + (lid & 15)) * ATP
                                           + ks * 16 + (lid >> 4) * 8) * 2));
#pragma unroll
                for (int jb = 0; jb < 4; jb++) {
                    uint32_t kb[4];
                    const int g = lid >> 3;
                    ldsm4(kb, s0 + (uint32_t)(((jb * 16 + (lid & 7) + ((g >> 1) << 3)) * ATP
                                               + ks * 16 + (g & 1) * 8) * 2));
                    mma16816h(sc[jb * 2],     qa, &kb[0]);
                    mma16816h(sc[jb * 2 + 1], qa, &kb[2]);
                }
            }

            // ---- causal mask ---------------------------------------------
            if (kt * 64 + 63 > qr0) {
                const int row0 = qr0 + (lid >> 2);
                const int row1 = row0 + 8;
#pragma unroll
                for (int nf = 0; nf < 8; nf++) {
                    const int colb = kt * 64 + nf * 8 + (lid & 3) * 2;
                    if (colb     > row0) sc[nf][0] = -1e30f;
                    if (colb + 1 > row0) sc[nf][1] = -1e30f;
                    if (colb     > row1) sc[nf][2] = -1e30f;
                    if (colb + 1 > row1) sc[nf][3] = -1e30f;
                }
            }

            // ---- online softmax (fp32) -----------------------------------
            float t0 = -1e30f, t1 = -1e30f;
#pragma unroll
            for (int nf = 0; nf < 8; nf++) {
                t0 = fmaxf(t0, fmaxf(sc[nf][0], sc[nf][1]));
                t1 = fmaxf(t1, fmaxf(sc[nf][2], sc[nf][3]));
            }
            t0 = fmaxf(t0, __shfl_xor_sync(0xffffffffu, t0, 1));
            t0 = fmaxf(t0, __shfl_xor_sync(0xffffffffu, t0, 2));
            t1 = fmaxf(t1, __shfl_xor_sync(0xffffffffu, t1, 1));
            t1 = fmaxf(t1, __shfl_xor_sync(0xffffffffu, t1, 2));

            const float n0 = fmaxf(mr0, t0), n1 = fmaxf(mr1, t1);
            const float a0 = exp2f(CL * (mr0 - n0));
            const float a1 = exp2f(CL * (mr1 - n1));
            mr0 = n0; mr1 = n1;

            float s0r = 0.f, s1r = 0.f;
#pragma unroll
            for (int nf = 0; nf < 8; nf++) {
                sc[nf][0] = exp2f(CL * (sc[nf][0] - n0)); s0r += sc[nf][0];
                sc[nf][1] = exp2f(CL * (sc[nf][1] - n0)); s0r += sc[nf][1];
                sc[nf][2] = exp2f(CL * (sc[nf][2] - n1)); s1r += sc[nf][2];
                sc[nf][3] = exp2f(CL * (sc[nf][3] - n1)); s1r += sc[nf][3];
            }
            s0r += __shfl_xor_sync(0xffffffffu, s0r, 1);
            s0r += __shfl_xor_sync(0xffffffffu, s0r, 2);
            s1r += __shfl_xor_sync(0xffffffffu, s1r, 1);
            s1r += __shfl_xor_sync(0xffffffffu, s1r, 2);
            lr0 = lr0 * a0 + s0r;
            lr1 = lr1 * a1 + s1r;

#pragma unroll
            for (int nf = 0; nf < 16; nf++) {
                o[nf][0] *= a0; o[nf][1] *= a0;
                o[nf][2] *= a1; o[nf][3] *= a1;
            }

            // ---- O += P V  (P = S c-frags reused as A-frags) --------------
#pragma unroll
            for (int k2 = 0; k2 < 4; k2++) {
                uint32_t pa[4];
                pa[0] = pack_h2(sc[2 * k2][0],     sc[2 * k2][1]);
                pa[1] = pack_h2(sc[2 * k2][2],     sc[2 * k2][3]);
                pa[2] = pack_h2(sc[2 * k2 + 1][0], sc[2 * k2 + 1][1]);
                pa[3] = pack_h2(sc[2 * k2 + 1][2], sc[2 * k2 + 1][3]);
#pragma unroll
                for (int vn = 0; vn < 8; vn++) {
                    uint32_t vb[4];
                    ldsm4t(vb, s0 + KV_TILE +
                        (uint32_t)(((k2 * 16 + (lid & 15)) * ATP
                                    + vn * 16 + (lid >> 4) * 8) * 2));
                    mma16816h(o[vn * 2],     pa, &vb[0]);
                    mma16816h(o[vn * 2 + 1], pa, &vb[2]);
                }
            }
        }
        __syncthreads();
    }

    // ---- epilogue: normalize, write bf16 hi/lo to [BT, 2048] ---------------
    const float inv0 = 1.f / lr0;
    const float inv1 = 1.f / lr1;
    const size_t t0g = (size_t)b * Tt + qt * 128 + wid * 16 + (lid >> 2);
#pragma unroll
    for (int nf = 0; nf < 16; nf++) {
        const int c = h * 128 + nf * 8 + (lid & 3) * 2;
        uint32_t hi, lo;
        hilo_bf2(o[nf][0] * inv0, o[nf][1] * inv0, hi, lo);
        *(uint32_t*)&OH[t0g * 2048 + c] = hi;
        *(uint32_t*)&OL[t0g * 2048 + c] = lo;
        hilo_bf2(o[nf][2] * inv1, o[nf][3] * inv1, hi, lo);
        *(uint32_t*)&OH[(t0g + 8) * 2048 + c] = hi;
        *(uint32_t*)&OL[(t0g + 8) * 2048 + c] = lo;
    }
}

// ===========================================================================
// host launch
// ===========================================================================
static inline void split(const float* in, __nv_bfloat16* hi, __nv_bfloat16* lo, int n) {
    split_bf16<<<n / 1024, 256>>>(in, hi, lo, n);
}

extern "C" void kernel_launch(void* const* d_in, const int* in_sizes, int n_in,
                              void* d_out, int out_size)
{
    const float* x     = (const float*)d_in[0];
    const float* W_kvD = (const float*)d_in[1];
    const float* W_qD  = (const float*)d_in[2];
    const float* W_kU  = (const float*)d_in[3];
    const float* W_vU  = (const float*)d_in[4];
    const float* W_qU  = (const float*)d_in[5];
    const float* W_rk  = (const float*)d_in[6];
    const float* W_rq  = (const float*)d_in[7];
    const float* W_o   = (const float*)d_in[8];
    float* out = (float*)d_out;

    float *dproj, *uk, *uq;
    cudaGetSymbolAddress((void**)&dproj, g_dproj);
    cudaGetSymbolAddress((void**)&uk,    g_uk);
    cudaGetSymbolAddress((void**)&uq,    g_uq);

    __nv_bfloat16 *xh, *xl, *dph, *dpl, *ath, *atl, *wh, *wl;
    cudaGetSymbolAddress((void**)&xh,  g_xh);
    cudaGetSymbolAddress((void**)&xl,  g_xl);
    cudaGetSymbolAddress((void**)&dph, g_dph);
    cudaGetSymbolAddress((void**)&dpl, g_dpl);
    cudaGetSymbolAddress((void**)&ath, g_ath);
    cudaGetSymbolAddress((void**)&atl, g_atl);
    cudaGetSymbolAddress((void**)&wh,  g_wh);
    cudaGetSymbolAddress((void**)&wl,  g_wl);

    __half *Q16, *K16, *V16;
    cudaGetSymbolAddress((void**)&Q16, g_Q16);
    cudaGetSymbolAddress((void**)&K16, g_K16);
    cudaGetSymbolAddress((void**)&V16, g_V16);

    cudaFuncSetAttribute(bgemm_tn, cudaFuncAttributeMaxDynamicSharedMemorySize, GEMM_SMEM);
    cudaFuncSetAttribute(attn_tc, cudaFuncAttributeMaxDynamicSharedMemorySize, ATTN2_SMEM);

    // ---- split inputs to bf16 hi/lo (weights into fused pools) ----
    split(x,     xh, xl, BT * 2048);
    split(W_kvD, wh + OFF_P1,               wl + OFF_P1,                512 * 2048);
    split(W_qD,  wh + OFF_P1 +  512 * 2048, wl + OFF_P1 +  512 * 2048,  512 * 2048);
    split(W_rk,  wh + OFF_P1 + 1024 * 2048, wl + OFF_P1 + 1024 * 2048, 1024 * 2048);
    split(W_kU,  wh + OFF_P2,               wl + OFF_P2,               1024 * 512);
    split(W_vU,  wh + OFF_P2 + 1024 * 512,  wl + OFF_P2 + 1024 * 512,  2048 * 512);
    split(W_qU,  wh + OFF_P3,               wl + OFF_P3,               1024 * 512);
    split(W_rq,  wh + OFF_P3 + 1024 * 512,  wl + OFF_P3 + 1024 * 512,  1024 * 512);
    split(W_o,   wh + OFF_PO,               wl + OFF_PO,               2048 * 2048);

    // ---- fused down projection ----
    bgemm_tn<<<dim3(16, 32), 256, GEMM_SMEM>>>(xh, xl, 2048,
        wh + OFF_P1, wl + OFF_P1, dproj, 2048, BT, 2048, 2048);

    split(dproj, dph, dpl, BT * 2048);

    // ---- fused up projections ----
    bgemm_tn<<<dim3(24, 32), 256, GEMM_SMEM>>>(dph, dpl, 2048,
        wh + OFF_P2, wl + OFF_P2, uk, 3072, BT, 3072, 512);
    bgemm_tn<<<dim3(16, 32), 256, GEMM_SMEM>>>(dph + 512, dpl + 512, 2048,
        wh + OFF_P3, wl + OFF_P3, uq, 2048, BT, 2048, 512);

    // ---- rope + head assembly (fp16) ----
    const int nqk = Bb * Tt * Hh * 32;
    assemble_qk_h<<<nqk / 256, 256>>>(uk, 3072, dproj + 1024, 2048, K16);
    assemble_qk_h<<<nqk / 256, 256>>>(uq, 2048, uq + 1024,    2048, Q16);
    assemble_v_h <<<nqk / 256, 256>>>(uk + 1024, 3072, V16);

    // ---- fp16 tensor-core attention (writes bf16 hi/lo directly) ----
    attn_tc<<<dim3(Tt / 128, Bb * Hh), 256, ATTN2_SMEM>>>(Q16, K16, V16, ath, atl);

    // ---- output projection ----
    bgemm_tn<<<dim3(16, 32), 256, GEMM_SMEM>>>(ath, atl, 2048,
        wh + OFF_PO, wl + OFF_PO, out, 2048, BT, 2048, 2048);
}

// round 10
// speedup vs baseline: 5.5337x; 1.7275x over previous
#include <cuda_runtime.h>
#include <cuda_bf16.h>
#include <cuda_fp16.h>
#include <stdint.h>
#include <math.h>

// ---------------------------------------------------------------------------
// MLA forward — all-fp16 tensor-core pipeline (fp32 accumulate everywhere).
//   GEMMs: single-product fp16 mma.sync HMMA.
//   Attention: fp16 HMMA flash attention (fp32 softmax/accum).
//   B=2, T=2048, C=2048, H=16, DH=128, L=512
//
// Fused layouts:
//   dproj [BT,2048] : cols 0-511 kv_d | 512-1023 q_d | 1024-2047 k_r(raw)
//   uk    [BT,3072] : cols 0-1023 k_c | 1024-3071 v
//   uq    [BT,2048] : cols 0-1023 q_c | 1024-2047 q_r(raw)
// Weight pool: P1=[W_kvD;W_qD;W_rk], P2=[W_kU;W_vU], P3=[W_qU;W_rq], PO=W_o
// ---------------------------------------------------------------------------

#define Bb 2
#define Tt 2048
#define Cc 2048
#define Hh 16
#define Dh 128
#define BT 4096   // B*T

// ---------------- fp32 scratch ----------------
__device__ float g_dproj[BT * 2048];
__device__ float g_uk   [BT * 3072];
__device__ float g_uq   [BT * 2048];

// ---------------- fp16 scratch ----------------
__device__ __half g_x16 [BT * 2048];
__device__ __half g_dp16[BT * 2048];
__device__ __half g_O16 [BT * 2048];   // attention output [BT, 2048]
__device__ __half g_Q16 [BT * 2048];   // [B,H,T,128]
__device__ __half g_K16 [BT * 2048];
__device__ __half g_V16 [BT * 2048];

// weight fp16 pool (element offsets)
#define OFF_P1 0
#define OFF_P2 4194304
#define OFF_P3 5767168
#define OFF_PO 6815744
#define WTOT   11010048
__device__ __half g_w16[WTOT];

// ===========================================================================
// helpers (base-target PTX only: cp.async, ldmatrix, mma.sync)
// ===========================================================================
__device__ __forceinline__ uint32_t smem_u32(const void* p) {
    uint32_t a;
    asm("{ .reg .u64 t; cvta.to.shared.u64 t, %1; cvt.u32.u64 %0, t; }"
        : "=r"(a) : "l"(p));
    return a;
}
__device__ __forceinline__ void cpasync16(uint32_t dst, const void* src) {
    asm volatile("cp.async.cg.shared.global [%0], [%1], 16;" :: "r"(dst), "l"(src));
}
#define CP_COMMIT() asm volatile("cp.async.commit_group;" ::: "memory")
template<int N> __device__ __forceinline__ void cp_wait() {
    asm volatile("cp.async.wait_group %0;" :: "n"(N) : "memory");
}
__device__ __forceinline__ void ldsm4(uint32_t* r, uint32_t addr) {
    asm volatile("ldmatrix.sync.aligned.m8n8.x4.shared.b16 {%0,%1,%2,%3}, [%4];"
        : "=r"(r[0]), "=r"(r[1]), "=r"(r[2]), "=r"(r[3]) : "r"(addr));
}
__device__ __forceinline__ void ldsm4t(uint32_t* r, uint32_t addr) {
    asm volatile("ldmatrix.sync.aligned.m8n8.x4.trans.shared.b16 {%0,%1,%2,%3}, [%4];"
        : "=r"(r[0]), "=r"(r[1]), "=r"(r[2]), "=r"(r[3]) : "r"(addr));
}
__device__ __forceinline__ void mma16816h(float* d, const uint32_t* a, const uint32_t* b) {
    asm volatile("mma.sync.aligned.m16n8k16.row.col.f32.f16.f16.f32 "
        "{%0,%1,%2,%3}, {%4,%5,%6,%7}, {%8,%9}, {%0,%1,%2,%3};"
        : "+f"(d[0]), "+f"(d[1]), "+f"(d[2]), "+f"(d[3])
        : "r"(a[0]), "r"(a[1]), "r"(a[2]), "r"(a[3]), "r"(b[0]), "r"(b[1]));
}
__device__ __forceinline__ uint32_t pack_h2(float a, float b) {
    __half2 h = __floats2half2_rn(a, b);
    return *(uint32_t*)&h;
}

// ===========================================================================
// fp32 -> fp16 convert
// ===========================================================================
__global__ void __launch_bounds__(256)
cvt_f16(const float* __restrict__ in, __half* __restrict__ out, int n)
{
    int i = (blockIdx.x * 256 + threadIdx.x) * 4;
    if (i >= n) return;
    float4 v = *(const float4*)&in[i];
    *(uint2*)&out[i] = make_uint2(pack_h2(v.x, v.y), pack_h2(v.z, v.w));
}

// ===========================================================================
// fp16 single-product mma.sync GEMM:  C[M,N] = A[M,K] @ W[N,K]^T
// CTA tile 128x128x32, 8 warps (2x4), warp tile 64x32.
// smem pitch 40 fp16; 2-stage cp.async double buffer; 2 CTAs/SM.
// ===========================================================================
#define Pp 40
#define TILE_B (128 * Pp * 2)      // 10240
#define HSTG_B (2 * TILE_B)        // 20480 (A, W)
#define GEMM_SMEM (2 * HSTG_B)     // 40960

__global__ void __launch_bounds__(256)
hgemm_tn(const __half* __restrict__ A_, int lda,
         const __half* __restrict__ W_,
         float* __restrict__ C, int ldc, int M, int N, int K)
{
    extern __shared__ char smem[];
    const uint32_t sb = smem_u32(smem);
    const int tid = threadIdx.x;
    const int lid = tid & 31;
    const int wid = tid >> 5;
    const int m0 = blockIdx.y * 128;
    const int n0 = blockIdx.x * 128;
    const int wm = (wid & 1) * 64;
    const int wn = (wid >> 1) * 32;

    float acc[4][4][4];
#pragma unroll
    for (int i = 0; i < 4; i++)
#pragma unroll
        for (int j = 0; j < 4; j++)
#pragma unroll
            for (int q = 0; q < 4; q++) acc[i][j][q] = 0.f;

    auto fill = [&](int stage, int k0) {
        const uint32_t s0 = sb + stage * HSTG_B;
#pragma unroll
        for (int it = 0; it < 2; it++) {
            const int idx = tid + it * 256;
            const int row = idx >> 2;
            const int ch  = idx & 3;
            const uint32_t so = (uint32_t)(row * Pp + ch * 8) * 2;
            cpasync16(s0 + so,          A_ + (size_t)(m0 + row) * lda + k0 + ch * 8);
            cpasync16(s0 + TILE_B + so, W_ + (size_t)(n0 + row) * K   + k0 + ch * 8);
        }
    };

    const int nk = K / 32;
    fill(0, 0); CP_COMMIT();

    for (int kt = 0; kt < nk; kt++) {
        const int cur = kt & 1;
        if (kt + 1 < nk) { fill(cur ^ 1, (kt + 1) * 32); CP_COMMIT(); cp_wait<1>(); }
        else             { cp_wait<0>(); }
        __syncthreads();

        const uint32_t s0 = sb + cur * HSTG_B;
#pragma unroll
        for (int ks = 0; ks < 2; ks++) {
            uint32_t aH[4][4], bH[2][4];
#pragma unroll
            for (int mi = 0; mi < 4; mi++)
                ldsm4(aH[mi], s0 + (uint32_t)(((wm + mi * 16 + (lid & 15)) * Pp
                                               + ks * 16 + (lid >> 4) * 8) * 2));
#pragma unroll
            for (int j = 0; j < 2; j++) {
                const int g = lid >> 3;
                ldsm4(bH[j], s0 + TILE_B +
                    (uint32_t)(((wn + j * 16 + (lid & 7) + ((g >> 1) << 3)) * Pp
                                + ks * 16 + (g & 1) * 8) * 2));
            }
#pragma unroll
            for (int mi = 0; mi < 4; mi++)
#pragma unroll
                for (int nj = 0; nj < 4; nj++)
                    mma16816h(acc[mi][nj], aH[mi], &bH[nj >> 1][(nj & 1) * 2]);
        }
        __syncthreads();
    }

#pragma unroll
    for (int mi = 0; mi < 4; mi++)
#pragma unroll
        for (int nj = 0; nj < 4; nj++) {
            const int r0 = m0 + wm + mi * 16 + (lid >> 2);
            const int c0 = n0 + wn + nj * 8 + (lid & 3) * 2;
            *(float2*)&C[(size_t)r0 * ldc + c0] =
                make_float2(acc[mi][nj][0], acc[mi][nj][1]);
            *(float2*)&C[(size_t)(r0 + 8) * ldc + c0] =
                make_float2(acc[mi][nj][2], acc[mi][nj][3]);
        }
}

// ===========================================================================
// RoPE + head assembly -> fp16 [B,H,T,128]
// ===========================================================================
__global__ void __launch_bounds__(256)
assemble_qk_h(const float* __restrict__ cpart, int cs,
              const float* __restrict__ rraw, int rs,
              __half* __restrict__ outp)
{
    const int idx = blockIdx.x * blockDim.x + threadIdx.x; // B*T*H*32
    const int p = idx & 31;
    const int h = (idx >> 5) & (Hh - 1);
    const int t = (idx >> 9) & (Tt - 1);
    const int b = idx >> 20;

    const size_t crow = (size_t)(b * Tt + t) * cs + (h << 6);
    const size_t rrow = (size_t)(b * Tt + t) * rs + (h << 6);
    const size_t ob = ((size_t)((b * Hh + h) * Tt + t) << 7);

    float2 cv = *(const float2*)&cpart[crow + 2 * p];
    *(uint32_t*)&outp[ob + 2 * p] = pack_h2(cv.x, cv.y);

    float2 rv = *(const float2*)&rraw[rrow + 2 * p];
    const int j0 = (h << 6) + 2 * p;
    const float kfc = -0.00899447225546836f;   // -ln(10000)/1024
    float freq = expf((float)j0 * kfc);
    float ang  = (float)t * freq;
    float s, c;
    sincosf(ang, &s, &c);
    *(uint32_t*)&outp[ob + 64 + 2 * p] =
        pack_h2(rv.x * c - rv.y * s, rv.y * c + rv.x * s);
}

__global__ void __launch_bounds__(256)
assemble_v_h(const float* __restrict__ vin, int vs, __half* __restrict__ vout)
{
    const int idx = blockIdx.x * blockDim.x + threadIdx.x; // B*H*T*32
    const int d4 = idx & 31;
    const int t  = (idx >> 5) & (Tt - 1);
    const int h  = (idx >> 16) & (Hh - 1);
    const int b  = idx >> 20;
    float4 v = *(const float4*)&vin[(size_t)(b * Tt + t) * vs + h * Dh + d4 * 4];
    *(uint2*)&vout[(size_t)idx * 4] =
        make_uint2(pack_h2(v.x, v.y), pack_h2(v.z, v.w));
}

// ===========================================================================
// fp16 tensor-core causal flash attention.
//   BQ=128 (8 warps x 16 rows), BKV=64, D=128. fp32 softmax + accumulators.
//   Output written as fp16 [BT, 2048] for the W_o GEMM.
// ===========================================================================
#define ATP 136
#define AQ_B   (128 * ATP * 2)         // 34816
#define KV_TILE (64 * ATP * 2)         // 17408
#define KV_STG  (2 * KV_TILE)          // 34816
#define ATTN2_SMEM (AQ_B + 2 * KV_STG) // 104448

__global__ void __launch_bounds__(256)
attn_tc(const __half* __restrict__ Qg, const __half* __restrict__ Kg,
        const __half* __restrict__ Vg, __half* __restrict__ O16)
{
    extern __shared__ char sm2[];
    const uint32_t sb = smem_u32(sm2);
    const int tid = threadIdx.x;
    const int lid = tid & 31;
    const int wid = tid >> 5;
    const int qt = gridDim.x - 1 - blockIdx.x;   // longest first
    const int bh = blockIdx.y;
    const int b = bh >> 4, h = bh & 15;
    const size_t gq = ((size_t)bh * Tt + qt * 128) * 128;
    const size_t gk = (size_t)bh * Tt * 128;

    // Q fill (one-shot)
#pragma unroll
    for (int it = 0; it < 8; it++) {
        const int idx = tid + it * 256;
        const int row = idx >> 4, ch = idx & 15;
        cpasync16(sb + row * (ATP * 2) + ch * 16, Qg + gq + row * 128 + ch * 8);
    }
    CP_COMMIT();

    auto fillKV = [&](int stg, int kt) {
        const uint32_t s0 = sb + AQ_B + stg * KV_STG;
        const size_t g0 = gk + (size_t)kt * 64 * 128;
#pragma unroll
        for (int it = 0; it < 4; it++) {
            const int idx = tid + it * 256;
            const int row = idx >> 4, ch = idx & 15;
            const uint32_t d = s0 + row * (ATP * 2) + ch * 16;
            cpasync16(d,           Kg + g0 + row * 128 + ch * 8);
            cpasync16(d + KV_TILE, Vg + g0 + row * 128 + ch * 8);
        }
    };

    float o[16][4];
#pragma unroll
    for (int i = 0; i < 16; i++)
#pragma unroll
        for (int q = 0; q < 4; q++) o[i][q] = 0.f;
    float mr0 = -1e30f, mr1 = -1e30f, lr0 = 0.f, lr1 = 0.f;
    const int qr0 = qt * 128 + wid * 16;
    const float CL = 0.12751149355487718f;  // (1/sqrt(128))*log2(e)

    const int ktmax = 2 * qt + 1;
    fillKV(0, 0); CP_COMMIT();

    for (int kt = 0; kt <= ktmax; kt++) {
        if (kt < ktmax) { fillKV((kt + 1) & 1, kt + 1); CP_COMMIT(); cp_wait<1>(); }
        else            { cp_wait<0>(); }
        __syncthreads();

        if (kt * 64 <= qr0 + 15) {
            const uint32_t s0 = sb + AQ_B + (kt & 1) * KV_STG;

            // ---- S = Q K^T ------------------------------------------------
            float sc[8][4];
#pragma unroll
            for (int i = 0; i < 8; i++)
#pragma unroll
                for (int q = 0; q < 4; q++) sc[i][q] = 0.f;

#pragma unroll
            for (int ks = 0; ks < 8; ks++) {
                uint32_t qa[4];
                ldsm4(qa, sb + (uint32_t)(((wid * 16 + (lid & 15)) * ATP
                                           + ks * 16 + (lid >> 4) * 8) * 2));
#pragma unroll
                for (int jb = 0; jb < 4; jb++) {
                    uint32_t kb[4];
                    const int g = lid >> 3;
                    ldsm4(kb, s0 + (uint32_t)(((jb * 16 + (lid & 7) + ((g >> 1) << 3)) * ATP
                                               + ks * 16 + (g & 1) * 8) * 2));
                    mma16816h(sc[jb * 2],     qa, &kb[0]);
                    mma16816h(sc[jb * 2 + 1], qa, &kb[2]);
                }
            }

            // ---- causal mask ---------------------------------------------
            if (kt * 64 + 63 > qr0) {
                const int row0 = qr0 + (lid >> 2);
                const int row1 = row0 + 8;
#pragma unroll
                for (int nf = 0; nf < 8; nf++) {
                    const int colb = kt * 64 + nf * 8 + (lid & 3) * 2;
                    if (colb     > row0) sc[nf][0] = -1e30f;
                    if (colb + 1 > row0) sc[nf][1] = -1e30f;
                    if (colb     > row1) sc[nf][2] = -1e30f;
                    if (colb + 1 > row1) sc[nf][3] = -1e30f;
                }
            }

            // ---- online softmax (fp32) -----------------------------------
            float t0 = -1e30f, t1 = -1e30f;
#pragma unroll
            for (int nf = 0; nf < 8; nf++) {
                t0 = fmaxf(t0, fmaxf(sc[nf][0], sc[nf][1]));
                t1 = fmaxf(t1, fmaxf(sc[nf][2], sc[nf][3]));
            }
            t0 = fmaxf(t0, __shfl_xor_sync(0xffffffffu, t0, 1));
            t0 = fmaxf(t0, __shfl_xor_sync(0xffffffffu, t0, 2));
            t1 = fmaxf(t1, __shfl_xor_sync(0xffffffffu, t1, 1));
            t1 = fmaxf(t1, __shfl_xor_sync(0xffffffffu, t1, 2));

            const float n0 = fmaxf(mr0, t0), n1 = fmaxf(mr1, t1);
            const float a0 = exp2f(CL * (mr0 - n0));
            const float a1 = exp2f(CL * (mr1 - n1));
            mr0 = n0; mr1 = n1;

            float s0r = 0.f, s1r = 0.f;
#pragma unroll
            for (int nf = 0; nf < 8; nf++) {
                sc[nf][0] = exp2f(CL * (sc[nf][0] - n0)); s0r += sc[nf][0];
                sc[nf][1] = exp2f(CL * (sc[nf][1] - n0)); s0r += sc[nf][1];
                sc[nf][2] = exp2f(CL * (sc[nf][2] - n1)); s1r += sc[nf][2];
                sc[nf][3] = exp2f(CL * (sc[nf][3] - n1)); s1r += sc[nf][3];
            }
            s0r += __shfl_xor_sync(0xffffffffu, s0r, 1);
            s0r += __shfl_xor_sync(0xffffffffu, s0r, 2);
            s1r += __shfl_xor_sync(0xffffffffu, s1r, 1);
            s1r += __shfl_xor_sync(0xffffffffu, s1r, 2);
            lr0 = lr0 * a0 + s0r;
            lr1 = lr1 * a1 + s1r;

#pragma unroll
            for (int nf = 0; nf < 16; nf++) {
                o[nf][0] *= a0; o[nf][1] *= a0;
                o[nf][2] *= a1; o[nf][3] *= a1;
            }

            // ---- O += P V  (P = S c-frags reused as A-frags) --------------
#pragma unroll
            for (int k2 = 0; k2 < 4; k2++) {
                uint32_t pa[4];
                pa[0] = pack_h2(sc[2 * k2][0],     sc[2 * k2][1]);
                pa[1] = pack_h2(sc[2 * k2][2],     sc[2 * k2][3]);
                pa[2] = pack_h2(sc[2 * k2 + 1][0], sc[2 * k2 + 1][1]);
                pa[3] = pack_h2(sc[2 * k2 + 1][2], sc[2 * k2 + 1][3]);
#pragma unroll
                for (int vn = 0; vn < 8; vn++) {
                    uint32_t vb[4];
                    ldsm4t(vb, s0 + KV_TILE +
                        (uint32_t)(((k2 * 16 + (lid & 15)) * ATP
                                    + vn * 16 + (lid >> 4) * 8) * 2));
                    mma16816h(o[vn * 2],     pa, &vb[0]);
                    mma16816h(o[vn * 2 + 1], pa, &vb[2]);
                }
            }
        }
        __syncthreads();
    }

    // ---- epilogue: normalize, write fp16 to [BT, 2048] ---------------------
    const float inv0 = 1.f / lr0;
    const float inv1 = 1.f / lr1;
    const size_t t0g = (size_t)b * Tt + qt * 128 + wid * 16 + (lid >> 2);
#pragma unroll
    for (int nf = 0; nf < 16; nf++) {
        const int c = h * 128 + nf * 8 + (lid & 3) * 2;
        *(uint32_t*)&O16[t0g * 2048 + c] =
            pack_h2(o[nf][0] * inv0, o[nf][1] * inv0);
        *(uint32_t*)&O16[(t0g + 8) * 2048 + c] =
            pack_h2(o[nf][2] * inv1, o[nf][3] * inv1);
    }
}

// ===========================================================================
// host launch
// ===========================================================================
static inline void cvt(const float* in, __half* out, int n) {
    cvt_f16<<<n / 1024, 256>>>(in, out, n);
}

extern "C" void kernel_launch(void* const* d_in, const int* in_sizes, int n_in,
                              void* d_out, int out_size)
{
    const float* x     = (const float*)d_in[0];
    const float* W_kvD = (const float*)d_in[1];
    const float* W_qD  = (const float*)d_in[2];
    const float* W_kU  = (const float*)d_in[3];
    const float* W_vU  = (const float*)d_in[4];
    const float* W_qU  = (const float*)d_in[5];
    const float* W_rk  = (const float*)d_in[6];
    const float* W_rq  = (const float*)d_in[7];
    const float* W_o   = (const float*)d_in[8];
    float* out = (float*)d_out;

    float *dproj, *uk, *uq;
    cudaGetSymbolAddress((void**)&dproj, g_dproj);
    cudaGetSymbolAddress((void**)&uk,    g_uk);
    cudaGetSymbolAddress((void**)&uq,    g_uq);

    __half *x16, *dp16, *O16, *Q16, *K16, *V16, *w16;
    cudaGetSymbolAddress((void**)&x16,  g_x16);
    cudaGetSymbolAddress((void**)&dp16, g_dp16);
    cudaGetSymbolAddress((void**)&O16,  g_O16);
    cudaGetSymbolAddress((void**)&Q16,  g_Q16);
    cudaGetSymbolAddress((void**)&K16,  g_K16);
    cudaGetSymbolAddress((void**)&V16,  g_V16);
    cudaGetSymbolAddress((void**)&w16,  g_w16);

    cudaFuncSetAttribute(hgemm_tn, cudaFuncAttributeMaxDynamicSharedMemorySize, GEMM_SMEM);
    cudaFuncSetAttribute(attn_tc, cudaFuncAttributeMaxDynamicSharedMemorySize, ATTN2_SMEM);

    // ---- convert inputs to fp16 (weights into fused pools) ----
    cvt(x,     x16,                          BT * 2048);
    cvt(W_kvD, w16 + OFF_P1,                 512 * 2048);
    cvt(W_qD,  w16 + OFF_P1 +  512 * 2048,   512 * 2048);
    cvt(W_rk,  w16 + OFF_P1 + 1024 * 2048,  1024 * 2048);
    cvt(W_kU,  w16 + OFF_P2,                1024 * 512);
    cvt(W_vU,  w16 + OFF_P2 + 1024 * 512,   2048 * 512);
    cvt(W_qU,  w16 + OFF_P3,                1024 * 512);
    cvt(W_rq,  w16 + OFF_P3 + 1024 * 512,   1024 * 512);
    cvt(W_o,   w16 + OFF_PO,                2048 * 2048);

    // ---- fused down projection: dproj = x @ [W_kvD;W_qD;W_rk]^T ----
    hgemm_tn<<<dim3(16, 32), 256, GEMM_SMEM>>>(x16, 2048,
        w16 + OFF_P1, dproj, 2048, BT, 2048, 2048);

    cvt(dproj, dp16, BT * 2048);

    // ---- fused up projections ----
    hgemm_tn<<<dim3(24, 32), 256, GEMM_SMEM>>>(dp16, 2048,
        w16 + OFF_P2, uk, 3072, BT, 3072, 512);
    hgemm_tn<<<dim3(16, 32), 256, GEMM_SMEM>>>(dp16 + 512, 2048,
        w16 + OFF_P3, uq, 2048, BT, 2048, 512);

    // ---- rope + head assembly (fp16) ----
    const int nqk = Bb * Tt * Hh * 32;
    assemble_qk_h<<<nqk / 256, 256>>>(uk, 3072, dproj + 1024, 2048, K16);
    assemble_qk_h<<<nqk / 256, 256>>>(uq, 2048, uq + 1024,    2048, Q16);
    assemble_v_h <<<nqk / 256, 256>>>(uk + 1024, 3072, V16);

    // ---- fp16 tensor-core attention (writes fp16 O directly) ----
    attn_tc<<<dim3(Tt / 128, Bb * Hh), 256, ATTN2_SMEM>>>(Q16, K16, V16, O16);

    // ---- output projection ----
    hgemm_tn<<<dim3(16, 32), 256, GEMM_SMEM>>>(O16, 2048,
        w16 + OFF_PO, out, 2048, BT, 2048, 2048);
}

// round 13
// speedup vs baseline: 5.7294x; 1.0354x over previous
#include <cuda_runtime.h>
#include <cuda_bf16.h>
#include <cuda_fp16.h>
#include <stdint.h>
#include <math.h>

// ---------------------------------------------------------------------------
// MLA forward, all-fp16 tensor-core pipeline with fp32 accumulation.
//   Projections: single-product fp16 mma.sync HMMA, dual fp16/fp32 epilogues.
//   Attention:   fp16 HMMA flash attention, fp32 softmax and accumulators.
//   Single fused input-conversion launch; single fused QKV-assembly launch.
//   Shapes: B=2, T=2048, C=2048, H=16, DH=128, L=512.
//
// Buffer roles:
//   krr32 [BT,2048] fp32, cols 1024.. valid  : raw k_r for rope
//   dp16  [BT,2048] fp16                     : kv_d | q_d | k_r
//   uk16  [BT,3072] fp16                     : k_c | v
//   qrr32 [BT,2048] fp32, cols 1024.. valid  : raw q_r for rope
//   uq16  [BT,2048] fp16                     : q_c | q_r
// Weight pool: P1=[W_kvD;W_qD;W_rk]  P2=[W_kU;W_vU]  P3=[W_qU;W_rq]  PO=W_o
// ---------------------------------------------------------------------------

#define Bb 2
#define Tt 2048
#define Cc 2048
#define Hh 16
#define Dh 128
#define BT 4096   // B*T

// fp32 scratch
__device__ float g_krr32[BT * 2048];
__device__ float g_qrr32[BT * 2048];

// fp16 scratch
__device__ __half g_x16 [BT * 2048];
__device__ __half g_dp16[BT * 2048];
__device__ __half g_uk16[BT * 3072];
__device__ __half g_uq16[BT * 2048];
__device__ __half g_O16 [BT * 2048];   // attention output, [BT, 2048]
__device__ __half g_Q16 [BT * 2048];   // [B,H,T,128]
__device__ __half g_K16 [BT * 2048];
__device__ __half g_V16 [BT * 2048];

// fp16 weight pool (element offsets)
#define OFF_P1 0
#define OFF_P2 4194304
#define OFF_P3 5767168
#define OFF_PO 6815744
#define WTOT   11010048
__device__ __half g_w16[WTOT];

// ===========================================================================
// PTX wrappers (base-target only: cp.async / ldmatrix / mma.sync)
// ===========================================================================
__device__ __forceinline__ uint32_t smem_u32(const void* p) {
    uint32_t a;
    asm("{ .reg .u64 t; cvta.to.shared.u64 t, %1; cvt.u32.u64 %0, t; }"
        : "=r"(a) : "l"(p));
    return a;
}
__device__ __forceinline__ void cpasync16(uint32_t dst, const void* src) {
    asm volatile("cp.async.cg.shared.global [%0], [%1], 16;" :: "r"(dst), "l"(src));
}
#define CP_COMMIT() asm volatile("cp.async.commit_group;" ::: "memory")
template<int N> __device__ __forceinline__ void cp_wait() {
    asm volatile("cp.async.wait_group %0;" :: "n"(N) : "memory");
}
__device__ __forceinline__ void ldsm4(uint32_t* r, uint32_t addr) {
    asm volatile("ldmatrix.sync.aligned.m8n8.x4.shared.b16 {%0,%1,%2,%3}, [%4];"
        : "=r"(r[0]), "=r"(r[1]), "=r"(r[2]), "=r"(r[3]) : "r"(addr));
}
__device__ __forceinline__ void ldsm4t(uint32_t* r, uint32_t addr) {
    asm volatile("ldmatrix.sync.aligned.m8n8.x4.trans.shared.b16 {%0,%1,%2,%3}, [%4];"
        : "=r"(r[0]), "=r"(r[1]), "=r"(r[2]), "=r"(r[3]) : "r"(addr));
}
__device__ __forceinline__ void mma16816h(float* d, const uint32_t* a, const uint32_t* b) {
    asm volatile("mma.sync.aligned.m16n8k16.row.col.f32.f16.f16.f32 "
        "{%0,%1,%2,%3}, {%4,%5,%6,%7}, {%8,%9}, {%0,%1,%2,%3};"
        : "+f"(d[0]), "+f"(d[1]), "+f"(d[2]), "+f"(d[3])
        : "r"(a[0]), "r"(a[1]), "r"(a[2]), "r"(a[3]), "r"(b[0]), "r"(b[1]));
}
__device__ __forceinline__ uint32_t pack_h2(float a, float b) {
    __half2 h = __floats2half2_rn(a, b);
    return *(uint32_t*)&h;
}

// ===========================================================================
// One-launch fp32->fp16 conversion of x plus all eight weights.
// One block converts 1024 contiguous elements.
// Segments (blocks): x 8192 | kvd 1024 | qd 1024 | rk 2048 | kU 512 |
//                    vU 1024 | qU 512 | rq 512 | Wo 4096  -> total 18944.
// ===========================================================================
#define CVT_BLOCKS 18944

__global__ void __launch_bounds__(256)
cvt_all(const float* __restrict__ x,   const float* __restrict__ kvd,
        const float* __restrict__ qd,  const float* __restrict__ rk,
        const float* __restrict__ kU,  const float* __restrict__ vU,
        const float* __restrict__ qU,  const float* __restrict__ rq,
        const float* __restrict__ Wo,
        __half* __restrict__ x16, __half* __restrict__ w16)
{
    const int blk = blockIdx.x;
    const float* src; __half* dst; int seg0;
    if      (blk <  8192) { src = x;   dst = x16;                    seg0 = blk;         }
    else if (blk <  9216) { src = kvd; dst = w16 + OFF_P1;           seg0 = blk -  8192; }
    else if (blk < 10240) { src = qd;  dst = w16 + OFF_P1 + 1048576; seg0 = blk -  9216; }
    else if (blk < 12288) { src = rk;  dst = w16 + OFF_P1 + 2097152; seg0 = blk - 10240; }
    else if (blk < 12800) { src = kU;  dst = w16 + OFF_P2;           seg0 = blk - 12288; }
    else if (blk < 13824) { src = vU;  dst = w16 + OFF_P2 + 524288;  seg0 = blk - 12800; }
    else if (blk < 14336) { src = qU;  dst = w16 + OFF_P3;           seg0 = blk - 13824; }
    else if (blk < 14848) { src = rq;  dst = w16 + OFF_P3 + 524288;  seg0 = blk - 14336; }
    else                  { src = Wo;  dst = w16 + OFF_PO;           seg0 = blk - 14848; }

    const int e = seg0 * 1024 + threadIdx.x * 4;
    float4 v = *(const float4*)&src[e];
    *(uint2*)&dst[e] = make_uint2(pack_h2(v.x, v.y), pack_h2(v.z, v.w));
}

// ===========================================================================
// fp16 single-product mma.sync GEMM:  C = A[M,K] @ W[N,K]^T.
// Dual epilogue: fp32 Cf written only by column-blocks with n0 >= cf_min
// (rope-source columns); fp16 Ch written when non-null.
// CTA tile 128x128x32, eight warps in 2x4, warp tile 64x32, pitch-40 smem,
// two-stage cp.async double buffer, two CTAs per SM.
// ===========================================================================
#define Pp 40
#define TILE_B (128 * Pp * 2)      // 10240 bytes
#define HSTG_B (2 * TILE_B)        // 20480 bytes: A tile + W tile
#define GEMM_SMEM (2 * HSTG_B)     // 40960 bytes

__global__ void __launch_bounds__(256)
hgemm_tn(const __half* __restrict__ A_, int lda,
         const __half* __restrict__ W_,
         float* __restrict__ Cf, int cf_min,
         __half* __restrict__ Ch,
         int ldc, int M, int N, int K)
{
    extern __shared__ char smem[];
    const uint32_t sb = smem_u32(smem);
    const int tid = threadIdx.x;
    const int lid = tid & 31;
    const int wid = tid >> 5;
    const int m0 = blockIdx.y * 128;
    const int n0 = blockIdx.x * 128;
    const int wm = (wid & 1) * 64;
    const int wn = (wid >> 1) * 32;

    float acc[4][4][4];
#pragma unroll
    for (int i = 0; i < 4; i++)
#pragma unroll
        for (int j = 0; j < 4; j++)
#pragma unroll
            for (int q = 0; q < 4; q++) acc[i][j][q] = 0.f;

    auto fill = [&](int stage, int k0) {
        const uint32_t s0 = sb + stage * HSTG_B;
#pragma unroll
        for (int it = 0; it < 2; it++) {
            const int idx = tid + it * 256;
            const int row = idx >> 2;
            const int ch  = idx & 3;
            const uint32_t so = (uint32_t)(row * Pp + ch * 8) * 2;
            cpasync16(s0 + so,          A_ + (size_t)(m0 + row) * lda + k0 + ch * 8);
            cpasync16(s0 + TILE_B + so, W_ + (size_t)(n0 + row) * K   + k0 + ch * 8);
        }
    };

    const int nk = K / 32;
    fill(0, 0); CP_COMMIT();

    for (int kt = 0; kt < nk; kt++) {
        const int cur = kt & 1;
        if (kt + 1 < nk) { fill(cur ^ 1, (kt + 1) * 32); CP_COMMIT(); cp_wait<1>(); }
        else             { cp_wait<0>(); }
        __syncthreads();

        const uint32_t s0 = sb + cur * HSTG_B;
#pragma unroll
        for (int ks = 0; ks < 2; ks++) {
            uint32_t aH[4][4], bH[2][4];
#pragma unroll
            for (int mi = 0; mi < 4; mi++)
                ldsm4(aH[mi], s0 + (uint32_t)(((wm + mi * 16 + (lid & 15)) * Pp
                                               + ks * 16 + (lid >> 4) * 8) * 2));
#pragma unroll
            for (int j = 0; j < 2; j++) {
                const int g = lid >> 3;
                ldsm4(bH[j], s0 + TILE_B +
                    (uint32_t)(((wn + j * 16 + (lid & 7) + ((g >> 1) << 3)) * Pp
                                + ks * 16 + (g & 1) * 8) * 2));
            }
#pragma unroll
            for (int mi = 0; mi < 4; mi++)
#pragma unroll
                for (int nj = 0; nj < 4; nj++)
                    mma16816h(acc[mi][nj], aH[mi], &bH[nj >> 1][(nj & 1) * 2]);
        }
        __syncthreads();
    }

    if (Cf && n0 >= cf_min) {
#pragma unroll
        for (int mi = 0; mi < 4; mi++)
#pragma unroll
            for (int nj = 0; nj < 4; nj++) {
                const int r0 = m0 + wm + mi * 16 + (lid >> 2);
                const int c0 = n0 + wn + nj * 8 + (lid & 3) * 2;
                *(float2*)&Cf[(size_t)r0 * ldc + c0] =
                    make_float2(acc[mi][nj][0], acc[mi][nj][1]);
                *(float2*)&Cf[(size_t)(r0 + 8) * ldc + c0] =
                    make_float2(acc[mi][nj][2], acc[mi][nj][3]);
            }
    }
    if (Ch) {
#pragma unroll
        for (int mi = 0; mi < 4; mi++)
#pragma unroll
            for (int nj = 0; nj < 4; nj++) {
                const int r0 = m0 + wm + mi * 16 + (lid >> 2);
                const int c0 = n0 + wn + nj * 8 + (lid & 3) * 2;
                *(uint32_t*)&Ch[(size_t)r0 * ldc + c0] =
                    pack_h2(acc[mi][nj][0], acc[mi][nj][1]);
                *(uint32_t*)&Ch[(size_t)(r0 + 8) * ldc + c0] =
                    pack_h2(acc[mi][nj][2], acc[mi][nj][3]);
            }
    }
}

// ===========================================================================
// One-launch QKV head assembly; blockIdx.y selects the role:
//   role 0: K = [k_c copy fp16 | rope(raw k_r fp32)]
//   role 1: Q = [q_c copy fp16 | rope(raw q_r fp32)]
//   role 2: V = uk16 cols 1024.. bit-copy into [B,H,T,128]
// ===========================================================================
__global__ void __launch_bounds__(256)
assemble_all(const __half* __restrict__ uk16, const float* __restrict__ krr32,
             const __half* __restrict__ uq16, const float* __restrict__ qrr32,
             __half* __restrict__ K16, __half* __restrict__ Q16,
             __half* __restrict__ V16)
{
    const int idx = blockIdx.x * blockDim.x + threadIdx.x; // 2M threads per role
    const int role = blockIdx.y;

    if (role == 2) {
        const int d4 = idx & 31;
        const int t  = (idx >> 5) & (Tt - 1);
        const int h  = (idx >> 16) & (Hh - 1);
        const int b  = idx >> 20;
        uint2 v = *(const uint2*)&uk16[(size_t)(b * Tt + t) * 3072 + 1024 + h * Dh + d4 * 4];
        *(uint2*)&V16[(size_t)idx * 4] = v;
        return;
    }

    const __half* cpart = (role == 0) ? uk16 : uq16;
    const float*  rraw  = (role == 0) ? (krr32 + 1024) : (qrr32 + 1024);
    const int     cs    = (role == 0) ? 3072 : 2048;
    __half*       outp  = (role == 0) ? K16 : Q16;

    const int p = idx & 31;
    const int h = (idx >> 5) & (Hh - 1);
    const int t = (idx >> 9) & (Tt - 1);
    const int b = idx >> 20;

    const size_t crow = (size_t)(b * Tt + t) * cs + (h << 6);
    const size_t rrow = (size_t)(b * Tt + t) * 2048 + (h << 6);
    const size_t ob = ((size_t)((b * Hh + h) * Tt + t) << 7);

    // first half-head: direct fp16 copy of the c-part
    *(uint32_t*)&outp[ob + 2 * p] = *(const uint32_t*)&cpart[crow + 2 * p];

    // second half-head: interleaved rope in fp32, then one rounding to fp16
    float2 rv = *(const float2*)&rraw[rrow + 2 * p];
    const int j0 = (h << 6) + 2 * p;
    const float kfc = -0.00899447225546836f;   // -ln(10000)/1024
    float freq = expf((float)j0 * kfc);
    float ang  = (float)t * freq;
    float s, c;
    sincosf(ang, &s, &c);
    *(uint32_t*)&outp[ob + 64 + 2 * p] =
        pack_h2(rv.x * c - rv.y * s, rv.y * c + rv.x * s);
}

// ===========================================================================
// fp16 tensor-core causal flash attention.
// BQ=128 (8 warps x 16 query rows), BKV=64, D=128; fp32 softmax/accum;
// double-buffered cp.async K/V; fp16 output in [BT, 2048] layout.
// ===========================================================================
#define ATP 136
#define AQ_B   (128 * ATP * 2)         // 34816
#define KV_TILE (64 * ATP * 2)         // 17408
#define KV_STG  (2 * KV_TILE)          // 34816
#define ATTN2_SMEM (AQ_B + 2 * KV_STG) // 104448

__global__ void __launch_bounds__(256)
attn_tc(const __half* __restrict__ Qg, const __half* __restrict__ Kg,
        const __half* __restrict__ Vg, __half* __restrict__ O16)
{
    extern __shared__ char sm2[];
    const uint32_t sb = smem_u32(sm2);
    const int tid = threadIdx.x;
    const int lid = tid & 31;
    const int wid = tid >> 5;
    const int qt = gridDim.x - 1 - blockIdx.x;   // schedule longest tiles first
    const int bh = blockIdx.y;
    const int b = bh >> 4, h = bh & 15;
    const size_t gq = ((size_t)bh * Tt + qt * 128) * 128;
    const size_t gk = (size_t)bh * Tt * 128;

    // one-shot Q tile fill
#pragma unroll
    for (int it = 0; it < 8; it++) {
        const int idx = tid + it * 256;
        const int row = idx >> 4, ch = idx & 15;
        cpasync16(sb + row * (ATP * 2) + ch * 16, Qg + gq + row * 128 + ch * 8);
    }
    CP_COMMIT();

    auto fillKV = [&](int stg, int kt) {
        const uint32_t s0 = sb + AQ_B + stg * KV_STG;
        const size_t g0 = gk + (size_t)kt * 64 * 128;
#pragma unroll
        for (int it = 0; it < 4; it++) {
            const int idx = tid + it * 256;
            const int row = idx >> 4, ch = idx & 15;
            const uint32_t d = s0 + row * (ATP * 2) + ch * 16;
            cpasync16(d,           Kg + g0 + row * 128 + ch * 8);
            cpasync16(d + KV_TILE, Vg + g0 + row * 128 + ch * 8);
        }
    };

    float o[16][4];
#pragma unroll
    for (int i = 0; i < 16; i++)
#pragma unroll
        for (int q = 0; q < 4; q++) o[i][q] = 0.f;
    float mr0 = -1e30f, mr1 = -1e30f, lr0 = 0.f, lr1 = 0.f;
    const int qr0 = qt * 128 + wid * 16;
    const float CL = 0.12751149355487718f;  // (1/sqrt(128)) * log2(e)

    const int ktmax = 2 * qt + 1;
    fillKV(0, 0); CP_COMMIT();

    for (int kt = 0; kt <= ktmax; kt++) {
        if (kt < ktmax) { fillKV((kt + 1) & 1, kt + 1); CP_COMMIT(); cp_wait<1>(); }
        else            { cp_wait<0>(); }
        __syncthreads();

        if (kt * 64 <= qr0 + 15) {   // this warp has at least one unmasked pair
            const uint32_t s0 = sb + AQ_B + (kt & 1) * KV_STG;

            // S = Q K^T
            float sc[8][4];
#pragma unroll
            for (int i = 0; i < 8; i++)
#pragma unroll
                for (int q = 0; q < 4; q++) sc[i][q] = 0.f;

#pragma unroll
            for (int ks = 0; ks < 8; ks++) {
                uint32_t qa[4];
                ldsm4(qa, sb + (uint32_t)(((wid * 16 + (lid & 15)) * ATP
                                           + ks * 16 + (lid >> 4) * 8) * 2));
#pragma unroll
                for (int jb = 0; jb < 4; jb++) {
                    uint32_t kb[4];
                    const int g = lid >> 3;
                    ldsm4(kb, s0 + (uint32_t)(((jb * 16 + (lid & 7) + ((g >> 1) << 3)) * ATP
                                               + ks * 16 + (g & 1) * 8) * 2));
                    mma16816h(sc[jb * 2],     qa, &kb[0]);
                    mma16816h(sc[jb * 2 + 1], qa, &kb[2]);
                }
            }

            // causal mask (only diagonal-crossing tiles)
            if (kt * 64 + 63 > qr0) {
                const int row0 = qr0 + (lid >> 2);
                const int row1 = row0 + 8;
#pragma unroll
                for (int nf = 0; nf < 8; nf++) {
                    const int colb = kt * 64 + nf * 8 + (lid & 3) * 2;
                    if (colb     > row0) sc[nf][0] = -1e30f;
                    if (colb + 1 > row0) sc[nf][1] = -1e30f;
                    if (colb     > row1) sc[nf][2] = -1e30f;
                    if (colb + 1 > row1) sc[nf][3] = -1e30f;
                }
            }

            // online softmax (fp32, quad-shuffle row reductions)
            float t0 = -1e30f, t1 = -1e30f;
#pragma unroll
            for (int nf = 0; nf < 8; nf++) {
                t0 = fmaxf(t0, fmaxf(sc[nf][0], sc[nf][1]));
                t1 = fmaxf(t1, fmaxf(sc[nf][2], sc[nf][3]));
            }
            t0 = fmaxf(t0, __shfl_xor_sync(0xffffffffu, t0, 1));
            t0 = fmaxf(t0, __shfl_xor_sync(0xffffffffu, t0, 2));
            t1 = fmaxf(t1, __shfl_xor_sync(0xffffffffu, t1, 1));
            t1 = fmaxf(t1, __shfl_xor_sync(0xffffffffu, t1, 2));

            const float n0 = fmaxf(mr0, t0), n1 = fmaxf(mr1, t1);
            const float a0 = exp2f(CL * (mr0 - n0));
            const float a1 = exp2f(CL * (mr1 - n1));
            mr0 = n0; mr1 = n1;

            float s0r = 0.f, s1r = 0.f;
#pragma unroll
            for (int nf = 0; nf < 8; nf++) {
                sc[nf][0] = exp2f(CL * (sc[nf][0] - n0)); s0r += sc[nf][0];
                sc[nf][1] = exp2f(CL * (sc[nf][1] - n0)); s0r += sc[nf][1];
                sc[nf][2] = exp2f(CL * (sc[nf][2] - n1)); s1r += sc[nf][2];
                sc[nf][3] = exp2f(CL * (sc[nf][3] - n1)); s1r += sc[nf][3];
            }
            s0r += __shfl_xor_sync(0xffffffffu, s0r, 1);
            s0r += __shfl_xor_sync(0xffffffffu, s0r, 2);
            s1r += __shfl_xor_sync(0xffffffffu, s1r, 1);
            s1r += __shfl_xor_sync(0xffffffffu, s1r, 2);
            lr0 = lr0 * a0 + s0r;
            lr1 = lr1 * a1 + s1r;

#pragma unroll
            for (int nf = 0; nf < 16; nf++) {
                o[nf][0] *= a0; o[nf][1] *= a0;
                o[nf][2] *= a1; o[nf][3] *= a1;
            }

            // O += P V, reusing the S c-fragments as A-fragments
#pragma unroll
            for (int k2 = 0; k2 < 4; k2++) {
                uint32_t pa[4];
                pa[0] = pack_h2(sc[2 * k2][0],     sc[2 * k2][1]);
                pa[1] = pack_h2(sc[2 * k2][2],     sc[2 * k2][3]);
                pa[2] = pack_h2(sc[2 * k2 + 1][0], sc[2 * k2 + 1][1]);
                pa[3] = pack_h2(sc[2 * k2 + 1][2], sc[2 * k2 + 1][3]);
#pragma unroll
                for (int vn = 0; vn < 8; vn++) {
                    uint32_t vb[4];
                    ldsm4t(vb, s0 + KV_TILE +
                        (uint32_t)(((k2 * 16 + (lid & 15)) * ATP
                                    + vn * 16 + (lid >> 4) * 8) * 2));
                    mma16816h(o[vn * 2],     pa, &vb[0]);
                    mma16816h(o[vn * 2 + 1], pa, &vb[2]);
                }
            }
        }
        __syncthreads();
    }

    // normalize and store fp16 rows into [BT, 2048]
    const float inv0 = 1.f / lr0;
    const float inv1 = 1.f / lr1;
    const size_t t0g = (size_t)b * Tt + qt * 128 + wid * 16 + (lid >> 2);
#pragma unroll
    for (int nf = 0; nf < 16; nf++) {
        const int c = h * 128 + nf * 8 + (lid & 3) * 2;
        *(uint32_t*)&O16[t0g * 2048 + c] =
            pack_h2(o[nf][0] * inv0, o[nf][1] * inv0);
        *(uint32_t*)&O16[(t0g + 8) * 2048 + c] =
            pack_h2(o[nf][2] * inv1, o[nf][3] * inv1);
    }
}

// ===========================================================================
// host-side launch sequence
// ===========================================================================
extern "C" void kernel_launch(void* const* d_in, const int* in_sizes, int n_in,
                              void* d_out, int out_size)
{
    const float* x     = (const float*)d_in[0];
    const float* W_kvD = (const float*)d_in[1];
    const float* W_qD  = (const float*)d_in[2];
    const float* W_kU  = (const float*)d_in[3];
    const float* W_vU  = (const float*)d_in[4];
    const float* W_qU  = (const float*)d_in[5];
    const float* W_rk  = (const float*)d_in[6];
    const float* W_rq  = (const float*)d_in[7];
    const float* W_o   = (const float*)d_in[8];
    float* out = (float*)d_out;

    float *krr32, *qrr32;
    cudaGetSymbolAddress((void**)&krr32, g_krr32);
    cudaGetSymbolAddress((void**)&qrr32, g_qrr32);

    __half *x16, *dp16, *uk16, *uq16, *O16, *Q16, *K16, *V16, *w16;
    cudaGetSymbolAddress((void**)&x16,  g_x16);
    cudaGetSymbolAddress((void**)&dp16, g_dp16);
    cudaGetSymbolAddress((void**)&uk16, g_uk16);
    cudaGetSymbolAddress((void**)&uq16, g_uq16);
    cudaGetSymbolAddress((void**)&O16,  g_O16);
    cudaGetSymbolAddress((void**)&Q16,  g_Q16);
    cudaGetSymbolAddress((void**)&K16,  g_K16);
    cudaGetSymbolAddress((void**)&V16,  g_V16);
    cudaGetSymbolAddress((void**)&w16,  g_w16);

    cudaFuncSetAttribute(hgemm_tn, cudaFuncAttributeMaxDynamicSharedMemorySize, GEMM_SMEM);
    cudaFuncSetAttribute(attn_tc, cudaFuncAttributeMaxDynamicSharedMemorySize, ATTN2_SMEM);

    // single conversion launch (x and all weights)
    cvt_all<<<CVT_BLOCKS, 256>>>(x, W_kvD, W_qD, W_rk, W_kU, W_vU, W_qU, W_rq,
                                 W_o, x16, w16);

    // down projection: fp16 everywhere + fp32 rope columns (>=1024)
    hgemm_tn<<<dim3(16, 32), 256, GEMM_SMEM>>>(x16, 2048, w16 + OFF_P1,
        krr32, 1024, dp16, 2048, BT, 2048, 2048);

    // up projections
    hgemm_tn<<<dim3(24, 32), 256, GEMM_SMEM>>>(dp16, 2048, w16 + OFF_P2,
        (float*)0, 0, uk16, 3072, BT, 3072, 512);
    hgemm_tn<<<dim3(16, 32), 256, GEMM_SMEM>>>(dp16 + 512, 2048, w16 + OFF_P3,
        qrr32, 1024, uq16, 2048, BT, 2048, 512);

    // single QKV assembly launch
    assemble_all<<<dim3(8192, 3), 256>>>(uk16, krr32, uq16, qrr32, K16, Q16, V16);

    // attention
    attn_tc<<<dim3(Tt / 128, Bb * Hh), 256, ATTN2_SMEM>>>(Q16, K16, V16, O16);

    // output projection (fp32 result)
    hgemm_tn<<<dim3(16, 32), 256, GEMM_SMEM>>>(O16, 2048, w16 + OFF_PO,
        out, 0, (__half*)0, 2048, BT, 2048, 2048);
}

// round 14
// speedup vs baseline: 6.3159x; 1.1024x over previous
#include <cuda_runtime.h>
#include <cuda_bf16.h>
#include <cuda_fp16.h>
#include <stdint.h>
#include <math.h>

// ---------------------------------------------------------------------------
// MLA forward, all-fp16 tensor-core pipeline with fp32 accumulation.
//   Projections: fp16 mma.sync HMMA, 4-stage cp.async ring, dual epilogues.
//   Attention:   fp16 HMMA flash attention, BKV=128, fp32 softmax/accum.
//   Single fused input-conversion launch; single fused QKV-assembly launch.
//   Shapes: B=2, T=2048, C=2048, H=16, DH=128, L=512.
// ---------------------------------------------------------------------------

#define Bb 2
#define Tt 2048
#define Cc 2048
#define Hh 16
#define Dh 128
#define BT 4096   // B*T

// fp32 scratch (rope sources)
__device__ float g_krr32[BT * 2048];
__device__ float g_qrr32[BT * 2048];

// fp16 scratch
__device__ __half g_x16 [BT * 2048];
__device__ __half g_dp16[BT * 2048];
__device__ __half g_uk16[BT * 3072];
__device__ __half g_uq16[BT * 2048];
__device__ __half g_O16 [BT * 2048];   // attention output, [BT, 2048]
__device__ __half g_Q16 [BT * 2048];   // [B,H,T,128]
__device__ __half g_K16 [BT * 2048];
__device__ __half g_V16 [BT * 2048];

// fp16 weight pool (element offsets)
#define OFF_P1 0
#define OFF_P2 4194304
#define OFF_P3 5767168
#define OFF_PO 6815744
#define WTOT   11010048
__device__ __half g_w16[WTOT];

// ===========================================================================
// PTX wrappers (base-target only: cp.async / ldmatrix / mma.sync)
// ===========================================================================
__device__ __forceinline__ uint32_t smem_u32(const void* p) {
    uint32_t a;
    asm("{ .reg .u64 t; cvta.to.shared.u64 t, %1; cvt.u32.u64 %0, t; }"
        : "=r"(a) : "l"(p));
    return a;
}
__device__ __forceinline__ void cpasync16(uint32_t dst, const void* src) {
    asm volatile("cp.async.cg.shared.global [%0], [%1], 16;" :: "r"(dst), "l"(src));
}
#define CP_COMMIT() asm volatile("cp.async.commit_group;" ::: "memory")
template<int N> __device__ __forceinline__ void cp_wait() {
    asm volatile("cp.async.wait_group %0;" :: "n"(N) : "memory");
}
__device__ __forceinline__ void ldsm4(uint32_t* r, uint32_t addr) {
    asm volatile("ldmatrix.sync.aligned.m8n8.x4.shared.b16 {%0,%1,%2,%3}, [%4];"
        : "=r"(r[0]), "=r"(r[1]), "=r"(r[2]), "=r"(r[3]) : "r"(addr));
}
__device__ __forceinline__ void ldsm4t(uint32_t* r, uint32_t addr) {
    asm volatile("ldmatrix.sync.aligned.m8n8.x4.trans.shared.b16 {%0,%1,%2,%3}, [%4];"
        : "=r"(r[0]), "=r"(r[1]), "=r"(r[2]), "=r"(r[3]) : "r"(addr));
}
__device__ __forceinline__ void mma16816h(float* d, const uint32_t* a, const uint32_t* b) {
    asm volatile("mma.sync.aligned.m16n8k16.row.col.f32.f16.f16.f32 "
        "{%0,%1,%2,%3}, {%4,%5,%6,%7}, {%8,%9}, {%0,%1,%2,%3};"
        : "+f"(d[0]), "+f"(d[1]), "+f"(d[2]), "+f"(d[3])
        : "r"(a[0]), "r"(a[1]), "r"(a[2]), "r"(a[3]), "r"(b[0]), "r"(b[1]));
}
__device__ __forceinline__ uint32_t pack_h2(float a, float b) {
    __half2 h = __floats2half2_rn(a, b);
    return *(uint32_t*)&h;
}

// ===========================================================================
// One-launch fp32->fp16 conversion (x + all eight weights); 1024 elems/block.
// ===========================================================================
#define CVT_BLOCKS 18944

__global__ void __launch_bounds__(256)
cvt_all(const float* __restrict__ x,   const float* __restrict__ kvd,
        const float* __restrict__ qd,  const float* __restrict__ rk,
        const float* __restrict__ kU,  const float* __restrict__ vU,
        const float* __restrict__ qU,  const float* __restrict__ rq,
        const float* __restrict__ Wo,
        __half* __restrict__ x16, __half* __restrict__ w16)
{
    const int blk = blockIdx.x;
    const float* src; __half* dst; int seg0;
    if      (blk <  8192) { src = x;   dst = x16;                    seg0 = blk;         }
    else if (blk <  9216) { src = kvd; dst = w16 + OFF_P1;           seg0 = blk -  8192; }
    else if (blk < 10240) { src = qd;  dst = w16 + OFF_P1 + 1048576; seg0 = blk -  9216; }
    else if (blk < 12288) { src = rk;  dst = w16 + OFF_P1 + 2097152; seg0 = blk - 10240; }
    else if (blk < 12800) { src = kU;  dst = w16 + OFF_P2;           seg0 = blk - 12288; }
    else if (blk < 13824) { src = vU;  dst = w16 + OFF_P2 + 524288;  seg0 = blk - 12800; }
    else if (blk < 14336) { src = qU;  dst = w16 + OFF_P3;           seg0 = blk - 13824; }
    else if (blk < 14848) { src = rq;  dst = w16 + OFF_P3 + 524288;  seg0 = blk - 14336; }
    else                  { src = Wo;  dst = w16 + OFF_PO;           seg0 = blk - 14848; }

    const int e = seg0 * 1024 + threadIdx.x * 4;
    float4 v = *(const float4*)&src[e];
    *(uint2*)&dst[e] = make_uint2(pack_h2(v.x, v.y), pack_h2(v.z, v.w));
}

// ===========================================================================
// fp16 mma.sync GEMM:  C = A[M,K] @ W[N,K]^T.  4-stage cp.async ring,
// ONE __syncthreads per K-iteration. Dual fp32/fp16 epilogues.
// CTA tile 128x128x32, 8 warps (2x4), warp tile 64x32, pitch-40 smem.
// __launch_bounds__(256,2) pins regs <=128 so 2 CTAs/SM.
// ===========================================================================
#define Pp 40
#define TILE_B (128 * Pp * 2)      // 10240 bytes
#define HSTG_B (2 * TILE_B)        // 20480 bytes per stage (A + W)
#define GEMM_SMEM (4 * HSTG_B)     // 81920 bytes, 4 stages

__global__ void __launch_bounds__(256, 2)
hgemm_tn(const __half* __restrict__ A_, int lda,
         const __half* __restrict__ W_,
         float* __restrict__ Cf, int cf_min,
         __half* __restrict__ Ch,
         int ldc, int M, int N, int K)
{
    extern __shared__ char smem[];
    const uint32_t sb = smem_u32(smem);
    const int tid = threadIdx.x;
    const int lid = tid & 31;
    const int wid = tid >> 5;
    const int m0 = blockIdx.y * 128;
    const int n0 = blockIdx.x * 128;
    const int wm = (wid & 1) * 64;
    const int wn = (wid >> 1) * 32;

    float acc[4][4][4];
#pragma unroll
    for (int i = 0; i < 4; i++)
#pragma unroll
        for (int j = 0; j < 4; j++)
#pragma unroll
            for (int q = 0; q < 4; q++) acc[i][j][q] = 0.f;

    auto fill = [&](int stage, int k0) {
        const uint32_t s0 = sb + stage * HSTG_B;
#pragma unroll
        for (int it = 0; it < 2; it++) {
            const int idx = tid + it * 256;
            const int row = idx >> 2;
            const int ch  = idx & 3;
            const uint32_t so = (uint32_t)(row * Pp + ch * 8) * 2;
            cpasync16(s0 + so,          A_ + (size_t)(m0 + row) * lda + k0 + ch * 8);
            cpasync16(s0 + TILE_B + so, W_ + (size_t)(n0 + row) * K   + k0 + ch * 8);
        }
    };

    const int nk = K / 32;      // >= 16 for all call sites
    fill(0, 0);  CP_COMMIT();
    fill(1, 32); CP_COMMIT();
    fill(2, 64); CP_COMMIT();

    for (int kt = 0; kt < nk; kt++) {
        const int rem = nk - 1 - kt;           // groups issued beyond kt
        if      (rem >= 2) cp_wait<2>();
        else if (rem == 1) cp_wait<1>();
        else               cp_wait<0>();
        __syncthreads();                        // stage kt%4 ready; frees stage (kt+3)%4

        if (kt + 3 < nk) { fill((kt + 3) & 3, (kt + 3) * 32); CP_COMMIT(); }

        const uint32_t s0 = sb + (kt & 3) * HSTG_B;
#pragma unroll
        for (int ks = 0; ks < 2; ks++) {
            uint32_t aH[4][4], bH[2][4];
#pragma unroll
            for (int mi = 0; mi < 4; mi++)
                ldsm4(aH[mi], s0 + (uint32_t)(((wm + mi * 16 + (lid & 15)) * Pp
                                               + ks * 16 + (lid >> 4) * 8) * 2));
#pragma unroll
            for (int j = 0; j < 2; j++) {
                const int g = lid >> 3;
                ldsm4(bH[j], s0 + TILE_B +
                    (uint32_t)(((wn + j * 16 + (lid & 7) + ((g >> 1) << 3)) * Pp
                                + ks * 16 + (g & 1) * 8) * 2));
            }
#pragma unroll
            for (int mi = 0; mi < 4; mi++)
#pragma unroll
                for (int nj = 0; nj < 4; nj++)
                    mma16816h(acc[mi][nj], aH[mi], &bH[nj >> 1][(nj & 1) * 2]);
        }
    }

    if (Cf && n0 >= cf_min) {
#pragma unroll
        for (int mi = 0; mi < 4; mi++)
#pragma unroll
            for (int nj = 0; nj < 4; nj++) {
                const int r0 = m0 + wm + mi * 16 + (lid >> 2);
                const int c0 = n0 + wn + nj * 8 + (lid & 3) * 2;
                *(float2*)&Cf[(size_t)r0 * ldc + c0] =
                    make_float2(acc[mi][nj][0], acc[mi][nj][1]);
                *(float2*)&Cf[(size_t)(r0 + 8) * ldc + c0] =
                    make_float2(acc[mi][nj][2], acc[mi][nj][3]);
            }
    }
    if (Ch) {
#pragma unroll
        for (int mi = 0; mi < 4; mi++)
#pragma unroll
            for (int nj = 0; nj < 4; nj++) {
                const int r0 = m0 + wm + mi * 16 + (lid >> 2);
                const int c0 = n0 + wn + nj * 8 + (lid & 3) * 2;
                *(uint32_t*)&Ch[(size_t)r0 * ldc + c0] =
                    pack_h2(acc[mi][nj][0], acc[mi][nj][1]);
                *(uint32_t*)&Ch[(size_t)(r0 + 8) * ldc + c0] =
                    pack_h2(acc[mi][nj][2], acc[mi][nj][3]);
            }
    }
}

// ===========================================================================
// One-launch QKV head assembly; blockIdx.y selects the role:
//   role 0: K = [k_c copy fp16 | rope(raw k_r fp32)]
//   role 1: Q = [q_c copy fp16 | rope(raw q_r fp32)]
//   role 2: V = uk16 cols 1024.. bit-copy into [B,H,T,128]
// ===========================================================================
__global__ void __launch_bounds__(256)
assemble_all(const __half* __restrict__ uk16, const float* __restrict__ krr32,
             const __half* __restrict__ uq16, const float* __restrict__ qrr32,
             __half* __restrict__ K16, __half* __restrict__ Q16,
             __half* __restrict__ V16)
{
    const int idx = blockIdx.x * blockDim.x + threadIdx.x;
    const int role = blockIdx.y;

    if (role == 2) {
        const int d4 = idx & 31;
        const int t  = (idx >> 5) & (Tt - 1);
        const int h  = (idx >> 16) & (Hh - 1);
        const int b  = idx >> 20;
        uint2 v = *(const uint2*)&uk16[(size_t)(b * Tt + t) * 3072 + 1024 + h * Dh + d4 * 4];
        *(uint2*)&V16[(size_t)idx * 4] = v;
        return;
    }

    const __half* cpart = (role == 0) ? uk16 : uq16;
    const float*  rraw  = (role == 0) ? (krr32 + 1024) : (qrr32 + 1024);
    const int     cs    = (role == 0) ? 3072 : 2048;
    __half*       outp  = (role == 0) ? K16 : Q16;

    const int p = idx & 31;
    const int h = (idx >> 5) & (Hh - 1);
    const int t = (idx >> 9) & (Tt - 1);
    const int b = idx >> 20;

    const size_t crow = (size_t)(b * Tt + t) * cs + (h << 6);
    const size_t rrow = (size_t)(b * Tt + t) * 2048 + (h << 6);
    const size_t ob = ((size_t)((b * Hh + h) * Tt + t) << 7);

    *(uint32_t*)&outp[ob + 2 * p] = *(const uint32_t*)&cpart[crow + 2 * p];

    float2 rv = *(const float2*)&rraw[rrow + 2 * p];
    const int j0 = (h << 6) + 2 * p;
    const float kfc = -0.00899447225546836f;   // -ln(10000)/1024
    float freq = expf((float)j0 * kfc);
    float ang  = (float)t * freq;
    float s, c;
    sincosf(ang, &s, &c);
    *(uint32_t*)&outp[ob + 64 + 2 * p] =
        pack_h2(rv.x * c - rv.y * s, rv.y * c + rv.x * s);
}

// ===========================================================================
// fp16 tensor-core causal flash attention, BKV=128.
// BQ=128 (8 warps x 16 query rows), BKV=128, D=128; fp32 softmax/accum;
// double-buffered cp.async K/V (2 stages); fp16 output in [BT, 2048].
// Halved per-work softmax overhead and sync count vs BKV=64.
// ===========================================================================
#define ATP 136
#define AQ_B    (128 * ATP * 2)        // 34816 : Q tile
#define KV_TILE (128 * ATP * 2)        // 34816 : one K (or V) tile
#define KV_STG  (2 * KV_TILE)          // 69632 : K+V per stage
#define ATTN2_SMEM (AQ_B + 2 * KV_STG) // 174080

__global__ void __launch_bounds__(256)
attn_tc(const __half* __restrict__ Qg, const __half* __restrict__ Kg,
        const __half* __restrict__ Vg, __half* __restrict__ O16)
{
    extern __shared__ char sm2[];
    const uint32_t sb = smem_u32(sm2);
    const int tid = threadIdx.x;
    const int lid = tid & 31;
    const int wid = tid >> 5;
    const int qt = gridDim.x - 1 - blockIdx.x;   // longest tiles first
    const int bh = blockIdx.y;
    const int b = bh >> 4, h = bh & 15;
    const size_t gq = ((size_t)bh * Tt + qt * 128) * 128;
    const size_t gk = (size_t)bh * Tt * 128;

    // one-shot Q tile fill
#pragma unroll
    for (int it = 0; it < 8; it++) {
        const int idx = tid + it * 256;
        const int row = idx >> 4, ch = idx & 15;
        cpasync16(sb + row * (ATP * 2) + ch * 16, Qg + gq + row * 128 + ch * 8);
    }
    CP_COMMIT();

    auto fillKV = [&](int stg, int kt) {
        const uint32_t s0 = sb + AQ_B + stg * KV_STG;
        const size_t g0 = gk + (size_t)kt * 128 * 128;
#pragma unroll
        for (int it = 0; it < 8; it++) {
            const int idx = tid + it * 256;
            const int row = idx >> 4, ch = idx & 15;
            const uint32_t d = s0 + row * (ATP * 2) + ch * 16;
            cpasync16(d,           Kg + g0 + row * 128 + ch * 8);
            cpasync16(d + KV_TILE, Vg + g0 + row * 128 + ch * 8);
        }
    };

    float o[16][4];
#pragma unroll
    for (int i = 0; i < 16; i++)
#pragma unroll
        for (int q = 0; q < 4; q++) o[i][q] = 0.f;
    float mr0 = -1e30f, mr1 = -1e30f, lr0 = 0.f, lr1 = 0.f;
    const int qr0 = qt * 128 + wid * 16;
    const float CL = 0.12751149355487718f;  // (1/sqrt(128)) * log2(e)

    const int ktmax = qt;                   // inclusive; BKV == BQ == 128
    fillKV(0, 0); CP_COMMIT();

    for (int kt = 0; kt <= ktmax; kt++) {
        if (kt < ktmax) { fillKV((kt + 1) & 1, kt + 1); CP_COMMIT(); cp_wait<1>(); }
        else            { cp_wait<0>(); }
        __syncthreads();

        const uint32_t s0 = sb + AQ_B + (kt & 1) * KV_STG;

        // ---- S = Q K^T  (16 x 128 per warp) --------------------------------
        float sc[16][4];
#pragma unroll
        for (int i = 0; i < 16; i++)
#pragma unroll
            for (int q = 0; q < 4; q++) sc[i][q] = 0.f;

#pragma unroll
        for (int ks = 0; ks < 8; ks++) {
            uint32_t qa[4];
            ldsm4(qa, sb + (uint32_t)(((wid * 16 + (lid & 15)) * ATP
                                       + ks * 16 + (lid >> 4) * 8) * 2));
#pragma unroll
            for (int jb = 0; jb < 8; jb++) {
                uint32_t kb[4];
                const int g = lid >> 3;
                ldsm4(kb, s0 + (uint32_t)(((jb * 16 + (lid & 7) + ((g >> 1) << 3)) * ATP
                                           + ks * 16 + (g & 1) * 8) * 2));
                mma16816h(sc[jb * 2],     qa, &kb[0]);
                mma16816h(sc[jb * 2 + 1], qa, &kb[2]);
            }
        }

        // ---- causal mask (only on the diagonal tile) -----------------------
        if (kt == ktmax) {
            const int row0 = qr0 + (lid >> 2);
            const int row1 = row0 + 8;
#pragma unroll
            for (int nf = 0; nf < 16; nf++) {
                const int colb = kt * 128 + nf * 8 + (lid & 3) * 2;
                if (colb     > row0) sc[nf][0] = -1e30f;
                if (colb + 1 > row0) sc[nf][1] = -1e30f;
                if (colb     > row1) sc[nf][2] = -1e30f;
                if (colb + 1 > row1) sc[nf][3] = -1e30f;
            }
        }

        // ---- online softmax (fp32) -----------------------------------------
        float t0 = -1e30f, t1 = -1e30f;
#pragma unroll
        for (int nf = 0; nf < 16; nf++) {
            t0 = fmaxf(t0, fmaxf(sc[nf][0], sc[nf][1]));
            t1 = fmaxf(t1, fmaxf(sc[nf][2], sc[nf][3]));
        }
        t0 = fmaxf(t0, __shfl_xor_sync(0xffffffffu, t0, 1));
        t0 = fmaxf(t0, __shfl_xor_sync(0xffffffffu, t0, 2));
        t1 = fmaxf(t1, __shfl_xor_sync(0xffffffffu, t1, 1));
        t1 = fmaxf(t1, __shfl_xor_sync(0xffffffffu, t1, 2));

        const float n0 = fmaxf(mr0, t0), n1 = fmaxf(mr1, t1);
        const float a0 = exp2f(CL * (mr0 - n0));
        const float a1 = exp2f(CL * (mr1 - n1));
        mr0 = n0; mr1 = n1;

        float s0r = 0.f, s1r = 0.f;
#pragma unroll
        for (int nf = 0; nf < 16; nf++) {
            sc[nf][0] = exp2f(CL * (sc[nf][0] - n0)); s0r += sc[nf][0];
            sc[nf][1] = exp2f(CL * (sc[nf][1] - n0)); s0r += sc[nf][1];
            sc[nf][2] = exp2f(CL * (sc[nf][2] - n1)); s1r += sc[nf][2];
            sc[nf][3] = exp2f(CL * (sc[nf][3] - n1)); s1r += sc[nf][3];
        }
        s0r += __shfl_xor_sync(0xffffffffu, s0r, 1);
        s0r += __shfl_xor_sync(0xffffffffu, s0r, 2);
        s1r += __shfl_xor_sync(0xffffffffu, s1r, 1);
        s1r += __shfl_xor_sync(0xffffffffu, s1r, 2);
        lr0 = lr0 * a0 + s0r;
        lr1 = lr1 * a1 + s1r;

#pragma unroll
        for (int nf = 0; nf < 16; nf++) {
            o[nf][0] *= a0; o[nf][1] *= a0;
            o[nf][2] *= a1; o[nf][3] *= a1;
        }

        // ---- O += P V  (S c-frags reused as A-frags) -----------------------
#pragma unroll
        for (int k2 = 0; k2 < 8; k2++) {
            uint32_t pa[4];
            pa[0] = pack_h2(sc[2 * k2][0],     sc[2 * k2][1]);
            pa[1] = pack_h2(sc[2 * k2][2],     sc[2 * k2][3]);
            pa[2] = pack_h2(sc[2 * k2 + 1][0], sc[2 * k2 + 1][1]);
            pa[3] = pack_h2(sc[2 * k2 + 1][2], sc[2 * k2 + 1][3]);
#pragma unroll
            for (int vn = 0; vn < 8; vn++) {
                uint32_t vb[4];
                ldsm4t(vb, s0 + KV_TILE +
                    (uint32_t)(((k2 * 16 + (lid & 15)) * ATP
                                + vn * 16 + (lid >> 4) * 8) * 2));
                mma16816h(o[vn * 2],     pa, &vb[0]);
                mma16816h(o[vn * 2 + 1], pa, &vb[2]);
            }
        }
        __syncthreads();
    }

    // ---- normalize and store fp16 rows into [BT, 2048] ---------------------
    const float inv0 = 1.f / lr0;
    const float inv1 = 1.f / lr1;
    const size_t t0g = (size_t)b * Tt + qt * 128 + wid * 16 + (lid >> 2);
#pragma unroll
    for (int nf = 0; nf < 16; nf++) {
        const int c = h * 128 + nf * 8 + (lid & 3) * 2;
        *(uint32_t*)&O16[t0g * 2048 + c] =
            pack_h2(o[nf][0] * inv0, o[nf][1] * inv0);
        *(uint32_t*)&O16[(t0g + 8) * 2048 + c] =
            pack_h2(o[nf][2] * inv1, o[nf][3] * inv1);
    }
}

// ===========================================================================
// host-side launch sequence
// ===========================================================================
extern "C" void kernel_launch(void* const* d_in, const int* in_sizes, int n_in,
                              void* d_out, int out_size)
{
    const float* x     = (const float*)d_in[0];
    const float* W_kvD = (const float*)d_in[1];
    const float* W_qD  = (const float*)d_in[2];
    const float* W_kU  = (const float*)d_in[3];
    const float* W_vU  = (const float*)d_in[4];
    const float* W_qU  = (const float*)d_in[5];
    const float* W_rk  = (const float*)d_in[6];
    const float* W_rq  = (const float*)d_in[7];
    const float* W_o   = (const float*)d_in[8];
    float* out = (float*)d_out;

    float *krr32, *qrr32;
    cudaGetSymbolAddress((void**)&krr32, g_krr32);
    cudaGetSymbolAddress((void**)&qrr32, g_qrr32);

    __half *x16, *dp16, *uk16, *uq16, *O16, *Q16, *K16, *V16, *w16;
    cudaGetSymbolAddress((void**)&x16,  g_x16);
    cudaGetSymbolAddress((void**)&dp16, g_dp16);
    cudaGetSymbolAddress((void**)&uk16, g_uk16);
    cudaGetSymbolAddress((void**)&uq16, g_uq16);
    cudaGetSymbolAddress((void**)&O16,  g_O16);
    cudaGetSymbolAddress((void**)&Q16,  g_Q16);
    cudaGetSymbolAddress((void**)&K16,  g_K16);
    cudaGetSymbolAddress((void**)&V16,  g_V16);
    cudaGetSymbolAddress((void**)&w16,  g_w16);

    cudaFuncSetAttribute(hgemm_tn, cudaFuncAttributeMaxDynamicSharedMemorySize, GEMM_SMEM);
    cudaFuncSetAttribute(attn_tc, cudaFuncAttributeMaxDynamicSharedMemorySize, ATTN2_SMEM);

    // single conversion launch (x and all weights)
    cvt_all<<<CVT_BLOCKS, 256>>>(x, W_kvD, W_qD, W_rk, W_kU, W_vU, W_qU, W_rq,
                                 W_o, x16, w16);

    // down projection: fp16 everywhere + fp32 rope columns (>=1024)
    hgemm_tn<<<dim3(16, 32), 256, GEMM_SMEM>>>(x16, 2048, w16 + OFF_P1,
        krr32, 1024, dp16, 2048, BT, 2048, 2048);

    // up projections
    hgemm_tn<<<dim3(24, 32), 256, GEMM_SMEM>>>(dp16, 2048, w16 + OFF_P2,
        (float*)0, 0, uk16, 3072, BT, 3072, 512);
    hgemm_tn<<<dim3(16, 32), 256, GEMM_SMEM>>>(dp16 + 512, 2048, w16 + OFF_P3,
        qrr32, 1024, uq16, 2048, BT, 2048, 512);

    // single QKV assembly launch
    assemble_all<<<dim3(8192, 3), 256>>>(uk16, krr32, uq16, qrr32, K16, Q16, V16);

    // attention (BKV=128)
    attn_tc<<<dim3(Tt / 128, Bb * Hh), 256, ATTN2_SMEM>>>(Q16, K16, V16, O16);

    // output projection (fp32 result)
    hgemm_tn<<<dim3(16, 32), 256, GEMM_SMEM>>>(O16, 2048, w16 + OFF_PO,
        out, 0, (__half*)0, 2048, BT, 2048, 2048);
}